// round 3
// baseline (speedup 1.0000x reference)
#include <cuda_runtime.h>
#include <cuda_bf16.h>

// Problem constants
// B=4, S=2048, H=16, dh=64, D=1024, M = B*S = 8192
// Inputs (metadata order):
//  0 Q_emb f32 [B,S,D]   1 K_emb f32 [B,S,D]   2 V_emb f32 [B,S,D]
//  3 Q_ini i32 [B,S] (UNUSED by reference)     4 K_ini i32 [B,S]
//  5 WQ f32 [D,D]  6 WK  7 WV  8 WO
// Output: f32 [B,S,D]

#define BB   4
#define SS   2048
#define HH   16
#define DH   64
#define DM   1024
#define MM   (BB*SS)          // 8192
#define NEG_BIG 1e10f

// ---------------- scratch (device globals; no allocations allowed) --------
__device__ float g_q[BB*HH*SS*DH];     // [BH, S, dh]
__device__ float g_k[BB*HH*SS*DH];
__device__ float g_v[BB*HH*SS*DH];
__device__ float g_ctx[BB*SS*DM];      // [B, S, D]
__device__ float g_vmean[BB*HH*DH];    // [BH, dh]

// =================== GEMM: C[8192,1024] = X[8192,1024] @ W[1024,1024] =====
// 128x128x8 tiles, double-buffered smem, 8x8 register micro-tile / thread.
// dst_sel 0/1/2 -> g_q/g_k/g_v in [BH,S,dh] layout; 3 -> Yplain row-major.
// src_sel 0 -> Xparam; 1 -> g_ctx.
__global__ __launch_bounds__(256, 2)
void gemm8192_kernel(const float* __restrict__ Xparam,
                     const float* __restrict__ W,
                     float* __restrict__ Yplain,
                     int src_sel, int dst_sel)
{
    const int K = DM, N = DM;
    const float* X = (src_sel == 1) ? g_ctx : Xparam;

    __shared__ float As[2][8][128];
    __shared__ float Bs[2][8][128];

    const int tid = threadIdx.x;
    const int tx  = tid & 15;
    const int ty  = tid >> 4;
    const int bm  = blockIdx.y * 128;
    const int bn  = blockIdx.x * 128;

    // global-load assignments
    const int arow = tid >> 1;             // 0..127
    const int akq  = (tid & 1) << 2;       // 0 or 4
    const int brow = tid >> 5;             // 0..7
    const int bcol = (tid & 31) << 2;      // 0..124

    const float* xp = X + (size_t)(bm + arow) * K + akq;
    const float* wp = W + (size_t)brow * N + bn + bcol;

    float acc[8][8];
    #pragma unroll
    for (int i = 0; i < 8; ++i)
        #pragma unroll
        for (int j = 0; j < 8; ++j) acc[i][j] = 0.f;

    // prologue: tile 0 -> buf 0
    float4 av = *(const float4*)xp;
    float4 bv = *(const float4*)wp;
    As[0][akq+0][arow] = av.x; As[0][akq+1][arow] = av.y;
    As[0][akq+2][arow] = av.z; As[0][akq+3][arow] = av.w;
    *(float4*)&Bs[0][brow][bcol] = bv;
    __syncthreads();

    for (int kt = 0; kt < K/8; ++kt) {
        const int buf = kt & 1;
        if (kt < K/8 - 1) {
            av = *(const float4*)(xp + (kt+1)*8);
            bv = *(const float4*)(wp + (size_t)(kt+1)*8*N);
        }
        #pragma unroll
        for (int k = 0; k < 8; ++k) {
            float4 a0 = *(const float4*)&As[buf][k][ty*4];
            float4 a1 = *(const float4*)&As[buf][k][64 + ty*4];
            float4 b0 = *(const float4*)&Bs[buf][k][tx*4];
            float4 b1 = *(const float4*)&Bs[buf][k][64 + tx*4];
            float ar[8] = {a0.x,a0.y,a0.z,a0.w,a1.x,a1.y,a1.z,a1.w};
            float br[8] = {b0.x,b0.y,b0.z,b0.w,b1.x,b1.y,b1.z,b1.w};
            #pragma unroll
            for (int i = 0; i < 8; ++i)
                #pragma unroll
                for (int j = 0; j < 8; ++j)
                    acc[i][j] += ar[i] * br[j];
        }
        if (kt < K/8 - 1) {
            const int nb = buf ^ 1;
            As[nb][akq+0][arow] = av.x; As[nb][akq+1][arow] = av.y;
            As[nb][akq+2][arow] = av.z; As[nb][akq+3][arow] = av.w;
            *(float4*)&Bs[nb][brow][bcol] = bv;
        }
        __syncthreads();
    }

    // epilogue
    #pragma unroll
    for (int i = 0; i < 8; ++i) {
        const int m = bm + ((i >> 2) << 6) + (ty << 2) + (i & 3);
        #pragma unroll
        for (int jh = 0; jh < 2; ++jh) {
            const int n0 = bn + (jh << 6) + (tx << 2);
            float4 v = make_float4(acc[i][jh*4+0], acc[i][jh*4+1],
                                   acc[i][jh*4+2], acc[i][jh*4+3]);
            if (dst_sel < 3) {
                float* Y = (dst_sel == 0) ? g_q : (dst_sel == 1) ? g_k : g_v;
                const int b = m >> 11, s = m & (SS-1);
                const int h = n0 >> 6, d = n0 & (DH-1);
                *(float4*)&Y[(size_t)(((b << 4) + h) * SS + s) * DH + d] = v;
            } else {
                *(float4*)&Yplain[(size_t)m * DM + n0] = v;
            }
        }
    }
}

// =================== vmean: mean over S of V per (bh, d) ==================
// Needed for rows whose entire visible key range is pad-masked: reference
// scores are all exactly -1e10 (fp32 absorption) -> softmax is uniform over
// ALL 2048 keys -> ctx row = mean of V over the full sequence.
__global__ void vmean_kernel()
{
    __shared__ float red[256];
    const int bh = blockIdx.x;
    const int d  = threadIdx.x & 63;
    const int sc = threadIdx.x >> 6;
    float acc = 0.f;
    const int base = (bh << 11) + (sc << 9);
    for (int s = 0; s < 512; ++s)
        acc += g_v[(size_t)(base + s) * DH + d];
    red[threadIdx.x] = acc;
    __syncthreads();
    if (sc == 0)
        g_vmean[(bh << 6) + d] =
            (red[d] + red[64+d] + red[128+d] + red[192+d]) * (1.0f/2048.0f);
}

// =================== flash attention per (bh, q-tile of 64) ===============
// 256 threads = 64 rows x 4 column-groups (16 cols each).
// Dynamic smem: Qs/Ks/Vs/Ps [64][68] + kini[64]  = 69888 B.
#define PADW 68
#define ATTN_SMEM ((4*64*PADW)*4 + 64*4)

__global__ __launch_bounds__(256)
void attn_kernel(const int* __restrict__ K_ini)
{
    extern __shared__ float sm[];
    float* Qs = sm;                       // [64][PADW]
    float* Ks = Qs + 64*PADW;
    float* Vs = Ks + 64*PADW;
    float* Ps = Vs + 64*PADW;
    int*   kini_s = (int*)(Ps + 64*PADW);

    const int tid = threadIdx.x;
    const int qt  = blockIdx.x;           // 0..31
    const int bh  = blockIdx.y;           // 0..63
    const int b   = bh >> 4;
    const int h   = bh & 15;
    const int r   = tid >> 2;             // row 0..63
    const int g   = tid & 3;              // column-group 0..3

    // load Q tile [64][64]
    #pragma unroll
    for (int i = 0; i < 4; ++i) {
        const int f   = tid + (i << 8);
        const int row = f >> 4;
        const int c4  = (f & 15) << 2;
        *(float4*)&Qs[row*PADW + c4] =
            *(const float4*)&g_q[(size_t)((bh << 11) + (qt << 6) + row) * DH + c4];
    }

    float m_r = -3.0e38f;   // running max (finite sentinel: exp(-3e38-x)=0)
    float l_r = 0.f;        // running denom
    float o[16];
    #pragma unroll
    for (int j = 0; j < 16; ++j) o[j] = 0.f;

    const int qg = (qt << 6) + r;         // global query index of this row

    for (int kt = 0; kt <= qt; ++kt) {    // causal: skip tiles fully in future
        // load K,V tiles + kini
        #pragma unroll
        for (int i = 0; i < 4; ++i) {
            const int f   = tid + (i << 8);
            const int row = f >> 4;
            const int c4  = (f & 15) << 2;
            const size_t gidx = (size_t)((bh << 11) + (kt << 6) + row) * DH + c4;
            *(float4*)&Ks[row*PADW + c4] = *(const float4*)&g_k[gidx];
            *(float4*)&Vs[row*PADW + c4] = *(const float4*)&g_v[gidx];
        }
        if (tid < 64) kini_s[tid] = K_ini[(b << 11) + (kt << 6) + tid];
        __syncthreads();

        // scores: s[j] = dot(Q[r], K[g*16+j]) over dh=64
        float s[16];
        #pragma unroll
        for (int j = 0; j < 16; ++j) s[j] = 0.f;
        #pragma unroll
        for (int k4 = 0; k4 < 16; ++k4) {
            float4 qv = *(const float4*)&Qs[r*PADW + (k4 << 2)];
            #pragma unroll
            for (int j = 0; j < 16; ++j) {
                float4 kv = *(const float4*)&Ks[((g << 4) + j)*PADW + (k4 << 2)];
                s[j] += qv.x*kv.x; s[j] += qv.y*kv.y;
                s[j] += qv.z*kv.z; s[j] += qv.w*kv.w;
            }
        }

        // scale + mask (replicate reference fp32 arithmetic: subtract 1e10)
        float tmax = -3.0e38f;
        #pragma unroll
        for (int j = 0; j < 16; ++j) {
            const int c  = (g << 4) + j;
            const int kc = (kt << 6) + c;
            float sv = s[j] * 0.125f;               // 1/sqrt(64)
            if (kc > qg || kini_s[c] == 0) sv -= NEG_BIG;
            s[j] = sv;
            tmax = fmaxf(tmax, sv);
        }
        // row max across the 4 threads of this row (lanes differ in bits 0,1)
        tmax = fmaxf(tmax, __shfl_xor_sync(0xffffffffu, tmax, 1));
        tmax = fmaxf(tmax, __shfl_xor_sync(0xffffffffu, tmax, 2));

        const float newm  = fmaxf(m_r, tmax);
        const float scale = __expf(m_r - newm);
        float lsum = 0.f;
        #pragma unroll
        for (int j = 0; j < 16; ++j) {
            const float p = __expf(s[j] - newm);
            Ps[r*PADW + (g << 4) + j] = p;
            lsum += p;
        }
        lsum += __shfl_xor_sync(0xffffffffu, lsum, 1);
        lsum += __shfl_xor_sync(0xffffffffu, lsum, 2);
        l_r = l_r * scale + lsum;
        m_r = newm;
        #pragma unroll
        for (int j = 0; j < 16; ++j) o[j] *= scale;
        __syncthreads();

        // ctx: o[d] += sum_c P[r][c] * V[c][g*16+d]
        #pragma unroll
        for (int c4 = 0; c4 < 16; ++c4) {
            float4 pv = *(const float4*)&Ps[r*PADW + (c4 << 2)];
            float pa[4] = {pv.x, pv.y, pv.z, pv.w};
            #pragma unroll
            for (int i = 0; i < 4; ++i) {
                const float p = pa[i];
                const float* vrow = &Vs[((c4 << 2) + i)*PADW + (g << 4)];
                #pragma unroll
                for (int j4 = 0; j4 < 4; ++j4) {
                    float4 vv = *(const float4*)&vrow[j4 << 2];
                    o[j4*4+0] += p * vv.x;
                    o[j4*4+1] += p * vv.y;
                    o[j4*4+2] += p * vv.z;
                    o[j4*4+3] += p * vv.w;
                }
            }
        }
        __syncthreads();
    }

    // epilogue -> ctx[b, s, h*64 + d]  (layout for the WO GEMM)
    float* dst = &g_ctx[(size_t)((b << 11) + (qt << 6) + r) * DM + (h << 6) + (g << 4)];
    if (m_r < -1e9f) {
        // fully masked visible range -> reference softmax is uniform over all
        // 2048 keys (masked scores are exactly -1e10 in fp32) -> mean of V.
        const float* vm = &g_vmean[(bh << 6) + (g << 4)];
        #pragma unroll
        for (int j4 = 0; j4 < 4; ++j4)
            *(float4*)&dst[j4 << 2] = *(const float4*)&vm[j4 << 2];
    } else {
        const float inv = 1.0f / l_r;
        #pragma unroll
        for (int j4 = 0; j4 < 4; ++j4) {
            float4 v = make_float4(o[j4*4+0]*inv, o[j4*4+1]*inv,
                                   o[j4*4+2]*inv, o[j4*4+3]*inv);
            *(float4*)&dst[j4 << 2] = v;
        }
    }
}

// ============================ launch ======================================
extern "C" void kernel_launch(void* const* d_in, const int* in_sizes, int n_in,
                              void* d_out, int out_size)
{
    const float* Q_emb = (const float*)d_in[0];
    const float* K_emb = (const float*)d_in[1];
    const float* V_emb = (const float*)d_in[2];
    const int*   K_ini = (const int*)  d_in[4];   // d_in[3] (Q_ini) unused
    const float* WQ    = (const float*)d_in[5];
    const float* WK    = (const float*)d_in[6];
    const float* WV    = (const float*)d_in[7];
    const float* WO    = (const float*)d_in[8];
    float* out = (float*)d_out;

    (void)in_sizes; (void)n_in; (void)out_size;

    cudaFuncSetAttribute(attn_kernel,
                         cudaFuncAttributeMaxDynamicSharedMemorySize, ATTN_SMEM);

    dim3 gg(DM/128, MM/128);   // (8, 64)
    gemm8192_kernel<<<gg, 256>>>(Q_emb, WQ, nullptr, 0, 0);   // -> g_q
    gemm8192_kernel<<<gg, 256>>>(K_emb, WK, nullptr, 0, 1);   // -> g_k
    gemm8192_kernel<<<gg, 256>>>(V_emb, WV, nullptr, 0, 2);   // -> g_v

    vmean_kernel<<<BB*HH, 256>>>();

    attn_kernel<<<dim3(SS/64, BB*HH), 256, ATTN_SMEM>>>(K_ini);

    gemm8192_kernel<<<gg, 256>>>(nullptr, WO, out, 1, 3);     // g_ctx @ WO -> out
}

// round 10
// speedup vs baseline: 1.0882x; 1.0882x over previous
#include <cuda_runtime.h>
#include <cuda_bf16.h>
#include <cstdint>

// Problem constants
// B=4, S=2048, H=16, dh=64, D=1024, M = B*S = 8192
// Inputs: 0 Q_emb f32  1 K_emb f32  2 V_emb f32  3 Q_ini i32 (unused)
//         4 K_ini i32  5 WQ  6 WK  7 WV  8 WO (all f32 [1024,1024])
// Output: f32 [B,S,D]
//
// NOTE: harness compiles via virtual arch compute_103 (no 'a'), so tcgen05
// PTX is unavailable. Tensor cores are reached via sm_80-era
// ldmatrix + mma.sync.m16n8k16 (HMMA), with a 3xBF16 split (hi/lo) for
// fp32-grade accuracy: X@W ~= Xhi@Whi + Xhi@Wlo + Xlo@Whi.

#define BB   4
#define SS   2048
#define HH   16
#define DH   64
#define DM   1024
#define MM   (BB*SS)          // 8192
#define NEG_BIG 1e10f

// ---------------- scratch (device globals; no allocations allowed) --------
__device__ float g_q[BB*HH*SS*DH];     // [BH, S, dh] fp32
__device__ float g_k[BB*HH*SS*DH];
__device__ float g_v[BB*HH*SS*DH];
__device__ float g_ctx[BB*SS*DM];      // [B, S, D]
__device__ float g_vmean[BB*HH*DH];    // [BH, dh]
__device__ __nv_bfloat16 g_xhi[MM*DM]; // split X (hi/lo), K-major [M,1024]
__device__ __nv_bfloat16 g_xlo[MM*DM];
__device__ __nv_bfloat16 g_wthi[DM*DM]; // split W^T (hi/lo), [N,K] K-major
__device__ __nv_bfloat16 g_wtlo[DM*DM];

// ======================= inline PTX helpers (compute_103-safe) ============
__device__ __forceinline__ uint32_t smem_u32(const void* p) {
    uint32_t a;
    asm("{ .reg .u64 t; cvta.to.shared.u64 t, %1; cvt.u32.u64 %0, t; }"
        : "=r"(a) : "l"(p));
    return a;
}
__device__ __forceinline__ void cp_async16(uint32_t dst, const void* src) {
    asm volatile("cp.async.cg.shared.global [%0], [%1], 16;"
                 :: "r"(dst), "l"(src) : "memory");
}
#define CP_COMMIT()  asm volatile("cp.async.commit_group;" ::: "memory")
#define CP_WAIT(n)   asm volatile("cp.async.wait_group %0;" :: "n"(n) : "memory")

__device__ __forceinline__ void ldsm_x4(uint32_t r[4], uint32_t addr) {
    asm volatile("ldmatrix.sync.aligned.m8n8.x4.shared.b16 {%0,%1,%2,%3}, [%4];"
                 : "=r"(r[0]), "=r"(r[1]), "=r"(r[2]), "=r"(r[3]) : "r"(addr));
}
// D(16x8,f32) += A(16x16,bf16 row) * B(16x8,bf16 col)
__device__ __forceinline__ void mma16816(float c[4], const uint32_t a[4],
                                         uint32_t b0, uint32_t b1) {
    asm volatile(
        "mma.sync.aligned.m16n8k16.row.col.f32.bf16.bf16.f32 "
        "{%0,%1,%2,%3}, {%4,%5,%6,%7}, {%8,%9}, {%0,%1,%2,%3};"
        : "+f"(c[0]), "+f"(c[1]), "+f"(c[2]), "+f"(c[3])
        : "r"(a[0]), "r"(a[1]), "r"(a[2]), "r"(a[3]), "r"(b0), "r"(b1));
}

// ======================= split-conversion kernels =========================
__global__ void conv_x_kernel(const float* __restrict__ src, int use_ctx)
{
    const float* X = use_ctx ? g_ctx : src;
    const size_t idx = (size_t)blockIdx.x * blockDim.x + threadIdx.x;  // float4 units
    float4 v = ((const float4*)X)[idx];
    __nv_bfloat16 h[4], l[4];
    float f[4] = {v.x, v.y, v.z, v.w};
    #pragma unroll
    for (int i = 0; i < 4; ++i) {
        h[i] = __float2bfloat16(f[i]);
        l[i] = __float2bfloat16(f[i] - __bfloat162float(h[i]));
    }
    ((__nv_bfloat162*)g_xhi)[idx*2+0] = __nv_bfloat162(h[0], h[1]);
    ((__nv_bfloat162*)g_xhi)[idx*2+1] = __nv_bfloat162(h[2], h[3]);
    ((__nv_bfloat162*)g_xlo)[idx*2+0] = __nv_bfloat162(l[0], l[1]);
    ((__nv_bfloat162*)g_xlo)[idx*2+1] = __nv_bfloat162(l[2], l[3]);
}

// W f32 [K,N] -> W^T hi/lo bf16 [N,K] (K-major == col-major B for mma.row.col)
__global__ void conv_w_kernel(const float* __restrict__ W)
{
    const int idx = blockIdx.x * blockDim.x + threadIdx.x;  // 0 .. 1024*256-1
    const int n  = idx >> 8;
    const int kq = (idx & 255) << 2;
    __nv_bfloat16 h[4], l[4];
    #pragma unroll
    for (int j = 0; j < 4; ++j) {
        float w = W[(size_t)(kq + j) * DM + n];
        h[j] = __float2bfloat16(w);
        l[j] = __float2bfloat16(w - __bfloat162float(h[j]));
    }
    const size_t o2 = ((size_t)n * DM + kq) >> 1;
    ((__nv_bfloat162*)g_wthi)[o2+0] = __nv_bfloat162(h[0], h[1]);
    ((__nv_bfloat162*)g_wthi)[o2+1] = __nv_bfloat162(h[2], h[3]);
    ((__nv_bfloat162*)g_wtlo)[o2+0] = __nv_bfloat162(l[0], l[1]);
    ((__nv_bfloat162*)g_wtlo)[o2+1] = __nv_bfloat162(l[2], l[3]);
}

// ============== HMMA GEMM: C[8192,1024] = X @ W (3xBF16 split) ============
// 128x128 CTA tile, K-chunks of 32, cp.async double-buffered SMEM.
// 8 warps = 2(M) x 4(N); warp tile 64x32 = 4x4 m16n8k16 fragments.
// SMEM rows padded to 80 B (32+8 bf16) -> conflict-free ldmatrix
// (rows 0..7 mod 128B: 0,80,32,112,64,16,96,48 - distinct quads).
#define MAT_BYTES (128*80)            // one matrix tile (hi or lo), 10240 B
#define BUFB      (4*MAT_BYTES)       // Ahi,Alo,Bhi,Blo = 40960 B
#define GEMM_SMEM (2*BUFB)            // double buffer = 81920 B

__global__ __launch_bounds__(256, 1)
void mma_gemm_kernel(float* __restrict__ Yplain, int dst_sel)
{
    extern __shared__ char sm[];
    const int tid  = threadIdx.x;
    const int lane = tid & 31;
    const int wid  = tid >> 5;
    const int wm   = wid >> 2;          // 0..1
    const int wn   = wid & 3;           // 0..3
    const int bm   = blockIdx.y * 128;
    const int bn   = blockIdx.x * 128;
    const uint32_t sbase = smem_u32(sm);

    float acc[4][4][4];
    #pragma unroll
    for (int i = 0; i < 4; ++i)
        #pragma unroll
        for (int j = 0; j < 4; ++j)
            #pragma unroll
            for (int t = 0; t < 4; ++t) acc[i][j][t] = 0.f;

    // ---- async loader: one K-chunk (32) of Ahi/Alo/Bhi/Blo into buffer b
    auto load_chunk = [&](int kc, int b) {
        const uint32_t base = sbase + b*BUFB;
        #pragma unroll
        for (int t = 0; t < 2; ++t) {
            const int idx = tid + (t << 8);
            const int r = idx >> 2, c = idx & 3;
            const uint32_t so = (uint32_t)(r*80 + c*16);
            const size_t ea = (size_t)(bm + r)*DM + kc*32 + c*8;  // bf16 elems
            const size_t eb = (size_t)(bn + r)*DM + kc*32 + c*8;
            cp_async16(base +              so, g_xhi  + ea);
            cp_async16(base +   MAT_BYTES + so, g_xlo  + ea);
            cp_async16(base + 2*MAT_BYTES + so, g_wthi + eb);
            cp_async16(base + 3*MAT_BYTES + so, g_wtlo + eb);
        }
        CP_COMMIT();
    };

    load_chunk(0, 0);

    for (int kc = 0; kc < 32; ++kc) {
        const int b = kc & 1;
        if (kc < 31) { load_chunk(kc + 1, b ^ 1); CP_WAIT(1); }
        else         { CP_WAIT(0); }
        __syncthreads();

        const uint32_t abase = sbase + b*BUFB;
        const uint32_t bbase = abase + 2*MAT_BYTES;

        #pragma unroll
        for (int ks = 0; ks < 2; ++ks) {
            const uint32_t colB = (uint32_t)(ks*32 + (lane >> 4)*16);

            uint32_t ahi[4][4], alo[4][4];
            #pragma unroll
            for (int i = 0; i < 4; ++i) {
                const uint32_t ad = abase +
                    (uint32_t)((wm*64 + i*16 + (lane & 15))*80) + colB;
                ldsm_x4(ahi[i], ad);
                ldsm_x4(alo[i], ad + MAT_BYTES);
            }
            uint32_t bhi[4][2], blo[4][2];
            #pragma unroll
            for (int jp = 0; jp < 2; ++jp) {
                uint32_t r4[4];
                const uint32_t bd = bbase +
                    (uint32_t)((wn*32 + jp*16 + (lane & 15))*80) + colB;
                ldsm_x4(r4, bd);
                bhi[2*jp+0][0] = r4[0]; bhi[2*jp+0][1] = r4[2];
                bhi[2*jp+1][0] = r4[1]; bhi[2*jp+1][1] = r4[3];
                ldsm_x4(r4, bd + MAT_BYTES);
                blo[2*jp+0][0] = r4[0]; blo[2*jp+0][1] = r4[2];
                blo[2*jp+1][0] = r4[1]; blo[2*jp+1][1] = r4[3];
            }
            #pragma unroll
            for (int i = 0; i < 4; ++i)
                #pragma unroll
                for (int j = 0; j < 4; ++j) {
                    mma16816(acc[i][j], ahi[i], bhi[j][0], bhi[j][1]);
                    mma16816(acc[i][j], ahi[i], blo[j][0], blo[j][1]);
                    mma16816(acc[i][j], alo[i], bhi[j][0], bhi[j][1]);
                }
        }
        __syncthreads();
    }

    // ---- epilogue: scatter fp32 accumulators
    const int tg = lane >> 2;       // row group 0..7
    const int t4 = lane & 3;
    #pragma unroll
    for (int i = 0; i < 4; ++i) {
        #pragma unroll
        for (int j = 0; j < 4; ++j) {
            const int m0 = bm + wm*64 + i*16 + tg;
            const int n0 = bn + wn*32 + j*8 + t4*2;
            #pragma unroll
            for (int half = 0; half < 2; ++half) {
                const int m = m0 + half*8;
                const float x = acc[i][j][half*2+0];
                const float y = acc[i][j][half*2+1];
                if (dst_sel < 3) {
                    float* Y = (dst_sel == 0) ? g_q : (dst_sel == 1) ? g_k : g_v;
                    const int bb = m >> 11, s = m & (SS-1);
                    const int h  = n0 >> 6, d = n0 & (DH-1);
                    float2* p = (float2*)&Y[(size_t)(((bb << 4) + h) * SS + s) * DH + d];
                    *p = make_float2(x, y);
                } else {
                    float2* p = (float2*)&Yplain[(size_t)m * DM + n0];
                    *p = make_float2(x, y);
                }
            }
        }
    }
}

// =================== vmean: mean over S of V per (bh, d) ==================
__global__ void vmean_kernel()
{
    __shared__ float red[512];
    const int bh = blockIdx.x;
    const int d  = threadIdx.x & 63;
    const int sc = threadIdx.x >> 6;          // 0..7
    float acc = 0.f;
    const int base = (bh << 11) + (sc << 8);
    #pragma unroll 8
    for (int s = 0; s < 256; ++s)
        acc += g_v[(size_t)(base + s) * DH + d];
    red[threadIdx.x] = acc;
    __syncthreads();
    if (sc == 0) {
        float t = 0.f;
        #pragma unroll
        for (int j = 0; j < 8; ++j) t += red[(j << 6) + d];
        g_vmean[(bh << 6) + d] = t * (1.0f/2048.0f);
    }
}

// =================== flash attention per (bh, q-tile of 64) ===============
#define PADW 68
#define ATTN_SMEM ((4*64*PADW)*4 + 64*4)

__global__ __launch_bounds__(256)
void attn_kernel(const int* __restrict__ K_ini)
{
    extern __shared__ float smf[];
    float* Qs = smf;
    float* Ks = Qs + 64*PADW;
    float* Vs = Ks + 64*PADW;
    float* Ps = Vs + 64*PADW;
    int*   kini_s = (int*)(Ps + 64*PADW);

    const int tid = threadIdx.x;
    const int qt  = blockIdx.x;
    const int bh  = blockIdx.y;
    const int b   = bh >> 4;
    const int h   = bh & 15;
    const int r   = tid >> 2;
    const int g   = tid & 3;

    #pragma unroll
    for (int i = 0; i < 4; ++i) {
        const int f   = tid + (i << 8);
        const int row = f >> 4;
        const int c4  = (f & 15) << 2;
        *(float4*)&Qs[row*PADW + c4] =
            *(const float4*)&g_q[(size_t)((bh << 11) + (qt << 6) + row) * DH + c4];
    }

    float m_r = -3.0e38f;
    float l_r = 0.f;
    float o[16];
    #pragma unroll
    for (int j = 0; j < 16; ++j) o[j] = 0.f;

    const int qg = (qt << 6) + r;

    for (int kt = 0; kt <= qt; ++kt) {
        #pragma unroll
        for (int i = 0; i < 4; ++i) {
            const int f   = tid + (i << 8);
            const int row = f >> 4;
            const int c4  = (f & 15) << 2;
            const size_t gidx = (size_t)((bh << 11) + (kt << 6) + row) * DH + c4;
            *(float4*)&Ks[row*PADW + c4] = *(const float4*)&g_k[gidx];
            *(float4*)&Vs[row*PADW + c4] = *(const float4*)&g_v[gidx];
        }
        if (tid < 64) kini_s[tid] = K_ini[(b << 11) + (kt << 6) + tid];
        __syncthreads();

        float s[16];
        #pragma unroll
        for (int j = 0; j < 16; ++j) s[j] = 0.f;
        #pragma unroll
        for (int k4 = 0; k4 < 16; ++k4) {
            float4 qv = *(const float4*)&Qs[r*PADW + (k4 << 2)];
            #pragma unroll
            for (int j = 0; j < 16; ++j) {
                float4 kv = *(const float4*)&Ks[((g << 4) + j)*PADW + (k4 << 2)];
                s[j] += qv.x*kv.x; s[j] += qv.y*kv.y;
                s[j] += qv.z*kv.z; s[j] += qv.w*kv.w;
            }
        }

        float tmax = -3.0e38f;
        #pragma unroll
        for (int j = 0; j < 16; ++j) {
            const int c  = (g << 4) + j;
            const int kc = (kt << 6) + c;
            float sv = s[j] * 0.125f;
            if (kc > qg || kini_s[c] == 0) sv -= NEG_BIG;
            s[j] = sv;
            tmax = fmaxf(tmax, sv);
        }
        tmax = fmaxf(tmax, __shfl_xor_sync(0xffffffffu, tmax, 1));
        tmax = fmaxf(tmax, __shfl_xor_sync(0xffffffffu, tmax, 2));

        const float newm  = fmaxf(m_r, tmax);
        const float scale = __expf(m_r - newm);
        float lsum = 0.f;
        #pragma unroll
        for (int j = 0; j < 16; ++j) {
            const float p = __expf(s[j] - newm);
            Ps[r*PADW + (g << 4) + j] = p;
            lsum += p;
        }
        lsum += __shfl_xor_sync(0xffffffffu, lsum, 1);
        lsum += __shfl_xor_sync(0xffffffffu, lsum, 2);
        l_r = l_r * scale + lsum;
        m_r = newm;
        #pragma unroll
        for (int j = 0; j < 16; ++j) o[j] *= scale;
        __syncthreads();

        #pragma unroll
        for (int c4 = 0; c4 < 16; ++c4) {
            float4 pv = *(const float4*)&Ps[r*PADW + (c4 << 2)];
            float pa[4] = {pv.x, pv.y, pv.z, pv.w};
            #pragma unroll
            for (int i = 0; i < 4; ++i) {
                const float p = pa[i];
                const float* vrow = &Vs[((c4 << 2) + i)*PADW + (g << 4)];
                #pragma unroll
                for (int j4 = 0; j4 < 4; ++j4) {
                    float4 vv = *(const float4*)&vrow[j4 << 2];
                    o[j4*4+0] += p * vv.x;
                    o[j4*4+1] += p * vv.y;
                    o[j4*4+2] += p * vv.z;
                    o[j4*4+3] += p * vv.w;
                }
            }
        }
        __syncthreads();
    }

    float* dst = &g_ctx[(size_t)((b << 11) + (qt << 6) + r) * DM + (h << 6) + (g << 4)];
    if (m_r < -1e9f) {
        const float* vm = &g_vmean[(bh << 6) + (g << 4)];
        #pragma unroll
        for (int j4 = 0; j4 < 4; ++j4)
            *(float4*)&dst[j4 << 2] = *(const float4*)&vm[j4 << 2];
    } else {
        const float inv = 1.0f / l_r;
        #pragma unroll
        for (int j4 = 0; j4 < 4; ++j4) {
            float4 v = make_float4(o[j4*4+0]*inv, o[j4*4+1]*inv,
                                   o[j4*4+2]*inv, o[j4*4+3]*inv);
            *(float4*)&dst[j4 << 2] = v;
        }
    }
}

// ============================ launch ======================================
extern "C" void kernel_launch(void* const* d_in, const int* in_sizes, int n_in,
                              void* d_out, int out_size)
{
    const float* Q_emb = (const float*)d_in[0];
    const float* K_emb = (const float*)d_in[1];
    const float* V_emb = (const float*)d_in[2];
    const int*   K_ini = (const int*)  d_in[4];
    const float* WQ    = (const float*)d_in[5];
    const float* WK    = (const float*)d_in[6];
    const float* WV    = (const float*)d_in[7];
    const float* WO    = (const float*)d_in[8];
    float* out = (float*)d_out;
    (void)in_sizes; (void)n_in; (void)out_size;

    cudaFuncSetAttribute(attn_kernel,
                         cudaFuncAttributeMaxDynamicSharedMemorySize, ATTN_SMEM);
    cudaFuncSetAttribute(mma_gemm_kernel,
                         cudaFuncAttributeMaxDynamicSharedMemorySize, GEMM_SMEM);

    const dim3 gg(DM/128, MM/128);          // (8, 64)
    const int convx_blocks = (MM*DM/4)/256; // 8192
    const int convw_blocks = (DM*256)/256;  // 1024

    conv_w_kernel<<<convw_blocks, 256>>>(WQ);
    conv_x_kernel<<<convx_blocks, 256>>>(Q_emb, 0);
    mma_gemm_kernel<<<gg, 256, GEMM_SMEM>>>(nullptr, 0);   // -> g_q

    conv_w_kernel<<<convw_blocks, 256>>>(WK);
    conv_x_kernel<<<convx_blocks, 256>>>(K_emb, 0);
    mma_gemm_kernel<<<gg, 256, GEMM_SMEM>>>(nullptr, 1);   // -> g_k

    conv_w_kernel<<<convw_blocks, 256>>>(WV);
    conv_x_kernel<<<convx_blocks, 256>>>(V_emb, 0);
    mma_gemm_kernel<<<gg, 256, GEMM_SMEM>>>(nullptr, 2);   // -> g_v

    vmean_kernel<<<BB*HH, 512>>>();
    attn_kernel<<<dim3(SS/64, BB*HH), 256, ATTN_SMEM>>>(K_ini);

    conv_w_kernel<<<convw_blocks, 256>>>(WO);
    conv_x_kernel<<<convx_blocks, 256>>>(nullptr, 1);      // g_ctx -> split
    mma_gemm_kernel<<<gg, 256, GEMM_SMEM>>>(out, 3);       // -> out
}

// round 11
// speedup vs baseline: 5.8808x; 5.4041x over previous
#include <cuda_runtime.h>
#include <cuda_bf16.h>
#include <cstdint>

// Problem constants
// B=4, S=2048, H=16, dh=64, D=1024, M = B*S = 8192
// Inputs: 0 Q_emb f32  1 K_emb f32  2 V_emb f32  3 Q_ini i32 (unused)
//         4 K_ini i32  5 WQ  6 WK  7 WV  8 WO (all f32 [1024,1024])
// Output: f32 [B,S,D]
//
// Harness compiles via virtual arch compute_103 (no 'a'): tcgen05 PTX is
// unavailable. All tensor work uses the sm_80-era path validated in R10:
// cp.async + ldmatrix(non-trans) + mma.sync.m16n8k16.bf16, with 3xBF16
// splits (hi/lo) for fp32-grade accuracy.

#define BB   4
#define SS   2048
#define HH   16
#define DH   64
#define DM   1024
#define MM   (BB*SS)          // 8192
#define NEG_BIG 1e10f

// ---------------- scratch (device globals; no allocations allowed) --------
__device__ float g_v[BB*HH*SS*DH];          // [BH,S,dh] fp32 (vmean + vt source)
__device__ float g_vmean[BB*HH*DH];         // [BH,dh]
__device__ __nv_bfloat16 g_qbhi[BB*HH*SS*DH]; // Q/8 split, [bh][s][dh]
__device__ __nv_bfloat16 g_qblo[BB*HH*SS*DH];
__device__ __nv_bfloat16 g_kbhi[BB*HH*SS*DH]; // K split, [bh][s][dh]
__device__ __nv_bfloat16 g_kblo[BB*HH*SS*DH];
__device__ __nv_bfloat16 g_vthi[BB*HH*SS*DH]; // V^T split, [bh][dh][s]
__device__ __nv_bfloat16 g_vtlo[BB*HH*SS*DH];
__device__ __nv_bfloat16 g_xhi[MM*DM];      // GEMM input X split, K-major
__device__ __nv_bfloat16 g_xlo[MM*DM];
__device__ __nv_bfloat16 g_wthi[DM*DM];     // W^T split, [N][K] K-major
__device__ __nv_bfloat16 g_wtlo[DM*DM];

// ======================= inline PTX helpers (compute_103-safe) ============
__device__ __forceinline__ uint32_t smem_u32(const void* p) {
    uint32_t a;
    asm("{ .reg .u64 t; cvta.to.shared.u64 t, %1; cvt.u32.u64 %0, t; }"
        : "=r"(a) : "l"(p));
    return a;
}
__device__ __forceinline__ void cp_async16(uint32_t dst, const void* src) {
    asm volatile("cp.async.cg.shared.global [%0], [%1], 16;"
                 :: "r"(dst), "l"(src) : "memory");
}
#define CP_COMMIT()  asm volatile("cp.async.commit_group;" ::: "memory")
#define CP_WAIT(n)   asm volatile("cp.async.wait_group %0;" :: "n"(n) : "memory")

__device__ __forceinline__ void ldsm_x4(uint32_t r[4], uint32_t addr) {
    asm volatile("ldmatrix.sync.aligned.m8n8.x4.shared.b16 {%0,%1,%2,%3}, [%4];"
                 : "=r"(r[0]), "=r"(r[1]), "=r"(r[2]), "=r"(r[3]) : "r"(addr));
}
// D(16x8,f32) += A(16x16,bf16 row) * B(16x8,bf16 col)
__device__ __forceinline__ void mma16816(float c[4], const uint32_t a[4],
                                         uint32_t b0, uint32_t b1) {
    asm volatile(
        "mma.sync.aligned.m16n8k16.row.col.f32.bf16.bf16.f32 "
        "{%0,%1,%2,%3}, {%4,%5,%6,%7}, {%8,%9}, {%0,%1,%2,%3};"
        : "+f"(c[0]), "+f"(c[1]), "+f"(c[2]), "+f"(c[3])
        : "r"(a[0]), "r"(a[1]), "r"(a[2]), "r"(a[3]), "r"(b0), "r"(b1));
}
__device__ __forceinline__ uint32_t pk2(__nv_bfloat16 lo, __nv_bfloat16 hi) {
    __nv_bfloat162 v(lo, hi);
    return *(uint32_t*)&v;
}

// ======================= split-conversion kernels =========================
__global__ void conv_x_kernel(const float* __restrict__ src)
{
    const size_t idx = (size_t)blockIdx.x * blockDim.x + threadIdx.x;  // float4 units
    float4 v = ((const float4*)src)[idx];
    __nv_bfloat16 h[4], l[4];
    float f[4] = {v.x, v.y, v.z, v.w};
    #pragma unroll
    for (int i = 0; i < 4; ++i) {
        h[i] = __float2bfloat16(f[i]);
        l[i] = __float2bfloat16(f[i] - __bfloat162float(h[i]));
    }
    ((__nv_bfloat162*)g_xhi)[idx*2+0] = __nv_bfloat162(h[0], h[1]);
    ((__nv_bfloat162*)g_xhi)[idx*2+1] = __nv_bfloat162(h[2], h[3]);
    ((__nv_bfloat162*)g_xlo)[idx*2+0] = __nv_bfloat162(l[0], l[1]);
    ((__nv_bfloat162*)g_xlo)[idx*2+1] = __nv_bfloat162(l[2], l[3]);
}

// W f32 [K,N] -> W^T hi/lo bf16 [N,K]
__global__ void conv_w_kernel(const float* __restrict__ W)
{
    const int idx = blockIdx.x * blockDim.x + threadIdx.x;
    const int n  = idx >> 8;
    const int kq = (idx & 255) << 2;
    __nv_bfloat16 h[4], l[4];
    #pragma unroll
    for (int j = 0; j < 4; ++j) {
        float w = W[(size_t)(kq + j) * DM + n];
        h[j] = __float2bfloat16(w);
        l[j] = __float2bfloat16(w - __bfloat162float(h[j]));
    }
    const size_t o2 = ((size_t)n * DM + kq) >> 1;
    ((__nv_bfloat162*)g_wthi)[o2+0] = __nv_bfloat162(h[0], h[1]);
    ((__nv_bfloat162*)g_wthi)[o2+1] = __nv_bfloat162(h[2], h[3]);
    ((__nv_bfloat162*)g_wtlo)[o2+0] = __nv_bfloat162(l[0], l[1]);
    ((__nv_bfloat162*)g_wtlo)[o2+1] = __nv_bfloat162(l[2], l[3]);
}

// ============== HMMA GEMM: C[8192,1024] = X @ W (3xBF16 split) ============
// Identical mainloop to the R10-validated kernel; epilogues per dst_sel:
//  0: Q -> g_qbhi/lo (pre-scaled by 0.125), [bh][s][dh] bf16 split
//  1: K -> g_kbhi/lo
//  2: V -> g_v fp32 [bh][s][dh]
//  3: plain fp32 row-major (final output)
#define MAT_BYTES (128*80)
#define BUFB      (4*MAT_BYTES)
#define GEMM_SMEM (2*BUFB)

__global__ __launch_bounds__(256, 1)
void mma_gemm_kernel(float* __restrict__ Yplain, int dst_sel)
{
    extern __shared__ char smg[];
    const int tid  = threadIdx.x;
    const int lane = tid & 31;
    const int wid  = tid >> 5;
    const int wm   = wid >> 2;
    const int wn   = wid & 3;
    const int bm   = blockIdx.y * 128;
    const int bn   = blockIdx.x * 128;
    const uint32_t sbase = smem_u32(smg);

    float acc[4][4][4];
    #pragma unroll
    for (int i = 0; i < 4; ++i)
        #pragma unroll
        for (int j = 0; j < 4; ++j)
            #pragma unroll
            for (int t = 0; t < 4; ++t) acc[i][j][t] = 0.f;

    auto load_chunk = [&](int kc, int b) {
        const uint32_t base = sbase + b*BUFB;
        #pragma unroll
        for (int t = 0; t < 2; ++t) {
            const int idx = tid + (t << 8);
            const int r = idx >> 2, c = idx & 3;
            const uint32_t so = (uint32_t)(r*80 + c*16);
            const size_t ea = (size_t)(bm + r)*DM + kc*32 + c*8;
            const size_t eb = (size_t)(bn + r)*DM + kc*32 + c*8;
            cp_async16(base +              so, g_xhi  + ea);
            cp_async16(base +   MAT_BYTES + so, g_xlo  + ea);
            cp_async16(base + 2*MAT_BYTES + so, g_wthi + eb);
            cp_async16(base + 3*MAT_BYTES + so, g_wtlo + eb);
        }
        CP_COMMIT();
    };

    load_chunk(0, 0);

    for (int kc = 0; kc < 32; ++kc) {
        const int b = kc & 1;
        if (kc < 31) { load_chunk(kc + 1, b ^ 1); CP_WAIT(1); }
        else         { CP_WAIT(0); }
        __syncthreads();

        const uint32_t abase = sbase + b*BUFB;
        const uint32_t bbase = abase + 2*MAT_BYTES;

        #pragma unroll
        for (int ks = 0; ks < 2; ++ks) {
            const uint32_t colB = (uint32_t)(ks*32 + (lane >> 4)*16);

            uint32_t ahi[4][4], alo[4][4];
            #pragma unroll
            for (int i = 0; i < 4; ++i) {
                const uint32_t ad = abase +
                    (uint32_t)((wm*64 + i*16 + (lane & 15))*80) + colB;
                ldsm_x4(ahi[i], ad);
                ldsm_x4(alo[i], ad + MAT_BYTES);
            }
            uint32_t bhi[4][2], blo[4][2];
            #pragma unroll
            for (int jp = 0; jp < 2; ++jp) {
                uint32_t r4[4];
                const uint32_t bd = bbase +
                    (uint32_t)((wn*32 + jp*16 + (lane & 15))*80) + colB;
                ldsm_x4(r4, bd);
                bhi[2*jp+0][0] = r4[0]; bhi[2*jp+0][1] = r4[2];
                bhi[2*jp+1][0] = r4[1]; bhi[2*jp+1][1] = r4[3];
                ldsm_x4(r4, bd + MAT_BYTES);
                blo[2*jp+0][0] = r4[0]; blo[2*jp+0][1] = r4[2];
                blo[2*jp+1][0] = r4[1]; blo[2*jp+1][1] = r4[3];
            }
            #pragma unroll
            for (int i = 0; i < 4; ++i)
                #pragma unroll
                for (int j = 0; j < 4; ++j) {
                    mma16816(acc[i][j], ahi[i], bhi[j][0], bhi[j][1]);
                    mma16816(acc[i][j], ahi[i], blo[j][0], blo[j][1]);
                    mma16816(acc[i][j], alo[i], bhi[j][0], bhi[j][1]);
                }
        }
        __syncthreads();
    }

    // ---- epilogue
    const int tg = lane >> 2;
    const int t4 = lane & 3;
    const float qs = (dst_sel == 0) ? 0.125f : 1.0f;
    #pragma unroll
    for (int i = 0; i < 4; ++i) {
        #pragma unroll
        for (int j = 0; j < 4; ++j) {
            const int m0 = bm + wm*64 + i*16 + tg;
            const int n0 = bn + wn*32 + j*8 + t4*2;
            #pragma unroll
            for (int half = 0; half < 2; ++half) {
                const int m = m0 + half*8;
                const float x = acc[i][j][half*2+0] * qs;
                const float y = acc[i][j][half*2+1] * qs;
                if (dst_sel <= 1) {
                    const int bb = m >> 11, s = m & (SS-1);
                    const int h  = n0 >> 6, d = n0 & (DH-1);
                    const size_t oi = ((size_t)((bb << 4) + h) * SS + s) * DH + d;
                    __nv_bfloat16 hx = __float2bfloat16(x);
                    __nv_bfloat16 hy = __float2bfloat16(y);
                    __nv_bfloat16 lx = __float2bfloat16(x - __bfloat162float(hx));
                    __nv_bfloat16 ly = __float2bfloat16(y - __bfloat162float(hy));
                    if (dst_sel == 0) {
                        *(__nv_bfloat162*)&g_qbhi[oi] = __nv_bfloat162(hx, hy);
                        *(__nv_bfloat162*)&g_qblo[oi] = __nv_bfloat162(lx, ly);
                    } else {
                        *(__nv_bfloat162*)&g_kbhi[oi] = __nv_bfloat162(hx, hy);
                        *(__nv_bfloat162*)&g_kblo[oi] = __nv_bfloat162(lx, ly);
                    }
                } else if (dst_sel == 2) {
                    const int bb = m >> 11, s = m & (SS-1);
                    const int h  = n0 >> 6, d = n0 & (DH-1);
                    *(float2*)&g_v[((size_t)((bb << 4) + h) * SS + s) * DH + d] =
                        make_float2(x, y);
                } else {
                    *(float2*)&Yplain[(size_t)m * DM + n0] = make_float2(x, y);
                }
            }
        }
    }
}

// =============== V^T transpose + bf16 split: g_v -> g_vthi/lo =============
__global__ void vt_split_kernel()
{
    __shared__ float t[64][65];
    const int bh = blockIdx.y;
    const int sb = blockIdx.x << 6;
    const int tid = threadIdx.x;
    #pragma unroll
    for (int i = 0; i < 4; ++i) {
        const int f = tid + (i << 8);
        const int s = f >> 4, d4 = (f & 15) << 2;
        float4 v = *(const float4*)&g_v[((size_t)bh*SS + sb + s)*DH + d4];
        t[s][d4+0] = v.x; t[s][d4+1] = v.y; t[s][d4+2] = v.z; t[s][d4+3] = v.w;
    }
    __syncthreads();
    const int d  = tid >> 2;
    const int s0 = (tid & 3) << 4;
    #pragma unroll
    for (int j = 0; j < 16; j += 2) {
        float v0 = t[s0+j][d], v1 = t[s0+j+1][d];
        __nv_bfloat16 h0 = __float2bfloat16(v0), h1 = __float2bfloat16(v1);
        const size_t oi = ((size_t)bh*DH + d)*SS + sb + s0 + j;
        *(__nv_bfloat162*)&g_vthi[oi] = __nv_bfloat162(h0, h1);
        *(__nv_bfloat162*)&g_vtlo[oi] = __nv_bfloat162(
            __float2bfloat16(v0 - __bfloat162float(h0)),
            __float2bfloat16(v1 - __bfloat162float(h1)));
    }
}

// =================== vmean: mean over S of V per (bh, d) ==================
__global__ void vmean_kernel()
{
    __shared__ float red[512];
    const int bh = blockIdx.x;
    const int d  = threadIdx.x & 63;
    const int sc = threadIdx.x >> 6;
    float acc = 0.f;
    const int base = (bh << 11) + (sc << 8);
    #pragma unroll 8
    for (int s = 0; s < 256; ++s)
        acc += g_v[(size_t)(base + s) * DH + d];
    red[threadIdx.x] = acc;
    __syncthreads();
    if (sc == 0) {
        float t = 0.f;
        #pragma unroll
        for (int j = 0; j < 8; ++j) t += red[(j << 6) + d];
        g_vmean[(bh << 6) + d] = t * (1.0f/2048.0f);
    }
}

// =================== HMMA flash attention =================================
// CTA = (bh, q-tile of 64 rows), 128 threads = 4 warps; warp w owns rows
// w*16..w*16+15. Q pre-scaled by 1/8 (exact). Scores: qhi*khi + qhi*klo +
// qlo*khi; PV: phi*vhi + phi*vlo + plo*vhi with P split in registers
// (score C-frag layout == A-frag layout).
#define ATT_ROWB 144                 // smem row stride (64 bf16 + 8 pad)
#define ATT_MATB (64*ATT_ROWB)       // 9216 per matrix
#define ATT_QHI  0
#define ATT_QLO  ATT_MATB
#define ATT_KV(b) (2*ATT_MATB + (b)*4*ATT_MATB)  // khi,klo,vhi,vlo per buf
#define ATT_KINI (2*ATT_MATB + 8*ATT_MATB)       // 92160
#define ATT_SMEM (ATT_KINI + 512)                // 92672

__global__ __launch_bounds__(128, 2)
void attn_kernel(const int* __restrict__ K_ini)
{
    extern __shared__ char attsm[];
    const uint32_t sb = smem_u32(attsm);
    const int tid  = threadIdx.x;
    const int lane = tid & 31;
    const int w    = tid >> 5;
    const int qt   = blockIdx.x;
    const int bh   = blockIdx.y;
    const int b    = bh >> 4;
    const int h    = bh & 15;

    const size_t qkbase = (size_t)bh * SS * DH;   // bf16 elems, [bh][s][dh]
    const size_t vtbase = (size_t)bh * DH * SS;   // [bh][dh][s]

    auto load_kv = [&](int kt, int bf) {
        const uint32_t kb = sb + ATT_KV(bf);
        #pragma unroll
        for (int i = 0; i < 4; ++i) {
            const int f = tid + (i << 7);
            const int r = f >> 3, c = f & 7;
            const uint32_t so = (uint32_t)(r*ATT_ROWB + c*16);
            const size_t gk = qkbase + (size_t)(kt*64 + r)*DH + c*8;
            const size_t gv = vtbase + (size_t)r*SS + kt*64 + c*8;
            cp_async16(kb +              so, g_kbhi + gk);
            cp_async16(kb +   ATT_MATB + so, g_kblo + gk);
            cp_async16(kb + 2*ATT_MATB + so, g_vthi + gv);
            cp_async16(kb + 3*ATT_MATB + so, g_vtlo + gv);
        }
        CP_COMMIT();
    };

    // ---- prologue: Q + K/V tile 0 (one cp.async group) + kini0
    #pragma unroll
    for (int i = 0; i < 4; ++i) {
        const int f = tid + (i << 7);
        const int r = f >> 3, c = f & 7;
        const uint32_t so = (uint32_t)(r*ATT_ROWB + c*16);
        const size_t gq = qkbase + (size_t)(qt*64 + r)*DH + c*8;
        cp_async16(sb + ATT_QHI + so, g_qbhi + gq);
        cp_async16(sb + ATT_QLO + so, g_qblo + gq);
    }
    load_kv(0, 0);
    if (tid < 16)
        ((int4*)(attsm + ATT_KINI))[tid] =
            ((const int4*)(K_ini + b*SS))[tid];
    CP_WAIT(0);
    __syncthreads();

    // ---- Q A-fragments (resident)
    uint32_t qhi[4][4], qlo[4][4];
    const uint32_t lrow16 = (uint32_t)((lane & 15) * ATT_ROWB);
    const uint32_t lcol   = (uint32_t)((lane >> 4) << 4);
    #pragma unroll
    for (int kd = 0; kd < 4; ++kd) {
        const uint32_t qa = sb + (uint32_t)(w*16*ATT_ROWB) + lrow16 + kd*32 + lcol;
        ldsm_x4(qhi[kd], qa + ATT_QHI);
        ldsm_x4(qlo[kd], qa + ATT_QLO);
    }

    float o[8][4];
    #pragma unroll
    for (int jd = 0; jd < 8; ++jd)
        #pragma unroll
        for (int e = 0; e < 4; ++e) o[jd][e] = 0.f;
    float mrow[2] = {-3.0e38f, -3.0e38f};
    float lrow[2] = {0.f, 0.f};

    const int qr_loc = w*16 + (lane >> 2);   // tile-local row (half0)

    for (int kt = 0; kt <= qt; ++kt) {
        const int buf = kt & 1;
        if (kt < qt) { load_kv(kt + 1, buf ^ 1); CP_WAIT(1); }
        else         { CP_WAIT(0); }
        __syncthreads();
        if (kt < qt && tid < 16)
            ((int4*)(attsm + ATT_KINI))[(buf ^ 1)*16 + tid] =
                ((const int4*)(K_ini + b*SS + (kt + 1)*64))[tid];

        // ---- scores S = Q.K^T (3-pass split), fp32 frags
        float s[8][4];
        #pragma unroll
        for (int jn = 0; jn < 8; ++jn)
            #pragma unroll
            for (int e = 0; e < 4; ++e) s[jn][e] = 0.f;

        const uint32_t kb = sb + ATT_KV(buf);
        #pragma unroll
        for (int nk = 0; nk < 4; ++nk) {
            #pragma unroll
            for (int kd = 0; kd < 4; ++kd) {
                uint32_t kh[4], kl[4];
                const uint32_t ad = kb + (uint32_t)(nk*16*ATT_ROWB) + lrow16
                                  + kd*32 + lcol;
                ldsm_x4(kh, ad);
                ldsm_x4(kl, ad + ATT_MATB);
                mma16816(s[nk*2+0], qhi[kd], kh[0], kh[2]);
                mma16816(s[nk*2+0], qhi[kd], kl[0], kl[2]);
                mma16816(s[nk*2+0], qlo[kd], kh[0], kh[2]);
                mma16816(s[nk*2+1], qhi[kd], kh[1], kh[3]);
                mma16816(s[nk*2+1], qhi[kd], kl[1], kl[3]);
                mma16816(s[nk*2+1], qlo[kd], kh[1], kh[3]);
            }
        }

        // ---- mask (pad + causal on diagonal tile), tile max
        const int* kini = (const int*)(attsm + ATT_KINI) + buf*64;
        const int diag = (kt == qt);
        float tmax[2] = {-3.0e38f, -3.0e38f};
        #pragma unroll
        for (int jn = 0; jn < 8; ++jn) {
            #pragma unroll
            for (int e = 0; e < 4; ++e) {
                const int col  = jn*8 + ((lane & 3) << 1) + (e & 1);
                const int half = e >> 1;
                bool masked = (kini[col] == 0);
                if (diag) masked = masked || (col > qr_loc + half*8);
                float sv = s[jn][e];
                if (masked) sv -= NEG_BIG;       // exact -1e10 (fp32 absorb)
                s[jn][e] = sv;
                tmax[half] = fmaxf(tmax[half], sv);
            }
        }
        #pragma unroll
        for (int half = 0; half < 2; ++half) {
            tmax[half] = fmaxf(tmax[half], __shfl_xor_sync(0xffffffffu, tmax[half], 1));
            tmax[half] = fmaxf(tmax[half], __shfl_xor_sync(0xffffffffu, tmax[half], 2));
        }
        const float nm0 = fmaxf(mrow[0], tmax[0]);
        const float nm1 = fmaxf(mrow[1], tmax[1]);
        const float sc0 = __expf(mrow[0] - nm0);
        const float sc1 = __expf(mrow[1] - nm1);
        mrow[0] = nm0; mrow[1] = nm1;

        // ---- exp + P split into A-frags (register-only)
        uint32_t aphi[4][4], aplo[4][4];
        float ls0 = 0.f, ls1 = 0.f;
        #pragma unroll
        for (int jn = 0; jn < 8; ++jn) {
            const float p0 = __expf(s[jn][0] - nm0);
            const float p1 = __expf(s[jn][1] - nm0);
            const float p2 = __expf(s[jn][2] - nm1);
            const float p3 = __expf(s[jn][3] - nm1);
            ls0 += p0 + p1; ls1 += p2 + p3;
            __nv_bfloat16 h0 = __float2bfloat16(p0);
            __nv_bfloat16 h1 = __float2bfloat16(p1);
            __nv_bfloat16 h2 = __float2bfloat16(p2);
            __nv_bfloat16 h3 = __float2bfloat16(p3);
            const int kp  = jn >> 1;
            const int sub = (jn & 1) << 1;
            aphi[kp][sub+0] = pk2(h0, h1);
            aphi[kp][sub+1] = pk2(h2, h3);
            aplo[kp][sub+0] = pk2(__float2bfloat16(p0 - __bfloat162float(h0)),
                                  __float2bfloat16(p1 - __bfloat162float(h1)));
            aplo[kp][sub+1] = pk2(__float2bfloat16(p2 - __bfloat162float(h2)),
                                  __float2bfloat16(p3 - __bfloat162float(h3)));
        }
        ls0 += __shfl_xor_sync(0xffffffffu, ls0, 1);
        ls0 += __shfl_xor_sync(0xffffffffu, ls0, 2);
        ls1 += __shfl_xor_sync(0xffffffffu, ls1, 1);
        ls1 += __shfl_xor_sync(0xffffffffu, ls1, 2);
        lrow[0] = lrow[0]*sc0 + ls0;
        lrow[1] = lrow[1]*sc1 + ls1;
        #pragma unroll
        for (int jd = 0; jd < 8; ++jd) {
            o[jd][0] *= sc0; o[jd][1] *= sc0;
            o[jd][2] *= sc1; o[jd][3] *= sc1;
        }

        // ---- O += P.V (3-pass split); V^T rows = dh, content = keys
        const uint32_t vb = kb + 2*ATT_MATB;
        #pragma unroll
        for (int nd = 0; nd < 4; ++nd) {
            #pragma unroll
            for (int kp = 0; kp < 4; ++kp) {
                uint32_t vh[4], vl[4];
                const uint32_t ad = vb + (uint32_t)(nd*16*ATT_ROWB) + lrow16
                                  + kp*32 + lcol;
                ldsm_x4(vh, ad);
                ldsm_x4(vl, ad + ATT_MATB);
                mma16816(o[nd*2+0], aphi[kp], vh[0], vh[2]);
                mma16816(o[nd*2+0], aphi[kp], vl[0], vl[2]);
                mma16816(o[nd*2+0], aplo[kp], vh[0], vh[2]);
                mma16816(o[nd*2+1], aphi[kp], vh[1], vh[3]);
                mma16816(o[nd*2+1], aphi[kp], vl[1], vl[3]);
                mma16816(o[nd*2+1], aplo[kp], vh[1], vh[3]);
            }
        }
        __syncthreads();   // protect buf reuse by next iteration's prefetch
    }

    // ---- epilogue: ctx hi/lo split straight into the WO-GEMM input
    #pragma unroll
    for (int half = 0; half < 2; ++half) {
        const int row = qr_loc + half*8;
        const size_t mg = (size_t)(b*SS + qt*64 + row);
        const float inv = 1.0f / lrow[half];
        const bool fullmask = (mrow[half] < -1e9f);  // all-visible-masked row
        #pragma unroll
        for (int jd = 0; jd < 8; ++jd) {
            const int d = jd*8 + ((lane & 3) << 1);
            float v0, v1;
            if (fullmask) {
                // reference: all scores exactly -1e10 -> uniform softmax over
                // ALL 2048 keys -> mean of V
                v0 = g_vmean[bh*64 + d];
                v1 = g_vmean[bh*64 + d + 1];
            } else {
                v0 = o[jd][half*2+0] * inv;
                v1 = o[jd][half*2+1] * inv;
            }
            __nv_bfloat16 h0 = __float2bfloat16(v0);
            __nv_bfloat16 h1 = __float2bfloat16(v1);
            const size_t oi = mg*DM + h*64 + d;
            *(__nv_bfloat162*)&g_xhi[oi] = __nv_bfloat162(h0, h1);
            *(__nv_bfloat162*)&g_xlo[oi] = __nv_bfloat162(
                __float2bfloat16(v0 - __bfloat162float(h0)),
                __float2bfloat16(v1 - __bfloat162float(h1)));
        }
    }
}

// ============================ launch ======================================
extern "C" void kernel_launch(void* const* d_in, const int* in_sizes, int n_in,
                              void* d_out, int out_size)
{
    const float* Q_emb = (const float*)d_in[0];
    const float* K_emb = (const float*)d_in[1];
    const float* V_emb = (const float*)d_in[2];
    const int*   K_ini = (const int*)  d_in[4];
    const float* WQ    = (const float*)d_in[5];
    const float* WK    = (const float*)d_in[6];
    const float* WV    = (const float*)d_in[7];
    const float* WO    = (const float*)d_in[8];
    float* out = (float*)d_out;
    (void)in_sizes; (void)n_in; (void)out_size;

    cudaFuncSetAttribute(mma_gemm_kernel,
                         cudaFuncAttributeMaxDynamicSharedMemorySize, GEMM_SMEM);
    cudaFuncSetAttribute(attn_kernel,
                         cudaFuncAttributeMaxDynamicSharedMemorySize, ATT_SMEM);

    const dim3 gg(DM/128, MM/128);          // (8, 64)
    const int convx_blocks = (MM*DM/4)/256; // 8192
    const int convw_blocks = (DM*256)/256;  // 1024

    conv_w_kernel<<<convw_blocks, 256>>>(WQ);
    conv_x_kernel<<<convx_blocks, 256>>>(Q_emb);
    mma_gemm_kernel<<<gg, 256, GEMM_SMEM>>>(nullptr, 0);   // -> Q/8 bf16 split

    conv_w_kernel<<<convw_blocks, 256>>>(WK);
    conv_x_kernel<<<convx_blocks, 256>>>(K_emb);
    mma_gemm_kernel<<<gg, 256, GEMM_SMEM>>>(nullptr, 1);   // -> K bf16 split

    conv_w_kernel<<<convw_blocks, 256>>>(WV);
    conv_x_kernel<<<convx_blocks, 256>>>(V_emb);
    mma_gemm_kernel<<<gg, 256, GEMM_SMEM>>>(nullptr, 2);   // -> g_v fp32

    vt_split_kernel<<<dim3(SS/64, BB*HH), 256>>>();        // -> V^T bf16 split
    vmean_kernel<<<BB*HH, 512>>>();

    attn_kernel<<<dim3(SS/64, BB*HH), 128, ATT_SMEM>>>(K_ini); // -> ctx split

    conv_w_kernel<<<convw_blocks, 256>>>(WO);
    mma_gemm_kernel<<<gg, 256, GEMM_SMEM>>>(out, 3);       // ctx @ WO -> out
}

// round 12
// speedup vs baseline: 7.9409x; 1.3503x over previous
#include <cuda_runtime.h>
#include <cuda_fp16.h>
#include <cstdint>

// Problem constants
// B=4, S=2048, H=16, dh=64, D=1024, M = B*S = 8192
// Inputs: 0 Q_emb f32  1 K_emb f32  2 V_emb f32  3 Q_ini i32 (unused)
//         4 K_ini i32  5 WQ  6 WK  7 WV  8 WO (all f32 [1024,1024])
// Output: f32 [B,S,D]
//
// Harness compiles via virtual arch compute_103 (no 'a'): tcgen05 is
// unavailable. Tensor path: cp.async + ldmatrix + mma.sync.m16n8k16.f16
// (validated layout from R10/R11), with asymmetric fp16 2-pass splits:
//   X@W    ~= (Xhi + Xlo)@fp16(W)        (err ~ 2^-12 from W)
//   Q.K^T  ~= (Qhi + Qlo).fp16(K)^T      (scores abs err ~2e-4)
//   P.V    ~= (Phi + Plo).fp16(V)        (err ~ 2^-12 from V)

#define BB   4
#define SS   2048
#define HH   16
#define DH   64
#define DM   1024
#define MM   (BB*SS)          // 8192
#define NEG_BIG 1e10f

// ---------------- scratch (device globals; no allocations allowed) --------
__device__ float g_v[BB*HH*SS*DH];        // [BH,S,dh] fp32 (vmean + vt source)
__device__ float g_vmean[BB*HH*DH];       // [BH,dh]
__device__ __half g_qhi[BB*HH*SS*DH];     // Q split (unscaled), [bh][s][dh]
__device__ __half g_qlo[BB*HH*SS*DH];
__device__ __half g_kh [BB*HH*SS*DH];     // K single fp16, [bh][s][dh]
__device__ __half g_vth[BB*HH*SS*DH];     // V^T single fp16, [bh][dh][s]
__device__ __half g_xhi[MM*DM];           // GEMM input X split, K-major
__device__ __half g_xlo[MM*DM];
__device__ __half g_wt [DM*DM];           // W^T single fp16, [N][K] K-major

// ======================= inline PTX helpers (compute_103-safe) ============
__device__ __forceinline__ uint32_t smem_u32(const void* p) {
    uint32_t a;
    asm("{ .reg .u64 t; cvta.to.shared.u64 t, %1; cvt.u32.u64 %0, t; }"
        : "=r"(a) : "l"(p));
    return a;
}
__device__ __forceinline__ void cp_async16(uint32_t dst, const void* src) {
    asm volatile("cp.async.cg.shared.global [%0], [%1], 16;"
                 :: "r"(dst), "l"(src) : "memory");
}
#define CP_COMMIT()  asm volatile("cp.async.commit_group;" ::: "memory")
#define CP_WAIT(n)   asm volatile("cp.async.wait_group %0;" :: "n"(n) : "memory")

__device__ __forceinline__ void ldsm_x4(uint32_t r[4], uint32_t addr) {
    asm volatile("ldmatrix.sync.aligned.m8n8.x4.shared.b16 {%0,%1,%2,%3}, [%4];"
                 : "=r"(r[0]), "=r"(r[1]), "=r"(r[2]), "=r"(r[3]) : "r"(addr));
}
// D(16x8,f32) += A(16x16,f16 row) * B(16x8,f16 col)
__device__ __forceinline__ void mma16816(float c[4], const uint32_t a[4],
                                         uint32_t b0, uint32_t b1) {
    asm volatile(
        "mma.sync.aligned.m16n8k16.row.col.f32.f16.f16.f32 "
        "{%0,%1,%2,%3}, {%4,%5,%6,%7}, {%8,%9}, {%0,%1,%2,%3};"
        : "+f"(c[0]), "+f"(c[1]), "+f"(c[2]), "+f"(c[3])
        : "r"(a[0]), "r"(a[1]), "r"(a[2]), "r"(a[3]), "r"(b0), "r"(b1));
}
__device__ __forceinline__ uint32_t pk2(__half lo, __half hi) {
    __half2 v(lo, hi);
    return *(uint32_t*)&v;
}

// ======================= split-conversion kernels =========================
// X f32 [M,1024] -> fp16 hi/lo
__global__ void conv_x_kernel(const float* __restrict__ src)
{
    const size_t idx = (size_t)blockIdx.x * blockDim.x + threadIdx.x;  // float4 units
    float4 v = ((const float4*)src)[idx];
    float f[4] = {v.x, v.y, v.z, v.w};
    __half h[4], l[4];
    #pragma unroll
    for (int i = 0; i < 4; ++i) {
        h[i] = __float2half_rn(f[i]);
        l[i] = __float2half_rn(f[i] - __half2float(h[i]));
    }
    ((__half2*)g_xhi)[idx*2+0] = __half2(h[0], h[1]);
    ((__half2*)g_xhi)[idx*2+1] = __half2(h[2], h[3]);
    ((__half2*)g_xlo)[idx*2+0] = __half2(l[0], l[1]);
    ((__half2*)g_xlo)[idx*2+1] = __half2(l[2], l[3]);
}

// W f32 [K,N] -> W^T single fp16 [N,K]
__global__ void conv_w_kernel(const float* __restrict__ W)
{
    const int idx = blockIdx.x * blockDim.x + threadIdx.x;
    const int n  = idx >> 8;
    const int kq = (idx & 255) << 2;
    __half h[4];
    #pragma unroll
    for (int j = 0; j < 4; ++j)
        h[j] = __float2half_rn(W[(size_t)(kq + j) * DM + n]);
    const size_t o2 = ((size_t)n * DM + kq) >> 1;
    ((__half2*)g_wt)[o2+0] = __half2(h[0], h[1]);
    ((__half2*)g_wt)[o2+1] = __half2(h[2], h[3]);
}

// ============== HMMA GEMM: C[8192,1024] = X @ W (fp16 2-pass) =============
// 128x128 CTA tile, K-chunks of 32, cp.async double-buffered SMEM.
// 8 warps = 2(M) x 4(N); warp tile 64x32 = 4x4 m16n8k16 fragments.
// SMEM rows padded to 80 B -> conflict-free ldmatrix (validated R10/R11).
// Buffers per stage: Xhi, Xlo, Wt (3 matrices).
#define MAT_BYTES (128*80)            // 10240 B
#define BUFB      (3*MAT_BYTES)       // 30720 B
#define GEMM_SMEM (2*BUFB)            // 61440 B

__global__ __launch_bounds__(256, 1)
void mma_gemm_kernel(float* __restrict__ Yplain, int dst_sel)
{
    extern __shared__ char smg[];
    const int tid  = threadIdx.x;
    const int lane = tid & 31;
    const int wid  = tid >> 5;
    const int wm   = wid >> 2;
    const int wn   = wid & 3;
    const int bm   = blockIdx.y * 128;
    const int bn   = blockIdx.x * 128;
    const uint32_t sbase = smem_u32(smg);

    float acc[4][4][4];
    #pragma unroll
    for (int i = 0; i < 4; ++i)
        #pragma unroll
        for (int j = 0; j < 4; ++j)
            #pragma unroll
            for (int t = 0; t < 4; ++t) acc[i][j][t] = 0.f;

    auto load_chunk = [&](int kc, int b) {
        const uint32_t base = sbase + b*BUFB;
        #pragma unroll
        for (int t = 0; t < 2; ++t) {
            const int idx = tid + (t << 8);
            const int r = idx >> 2, c = idx & 3;
            const uint32_t so = (uint32_t)(r*80 + c*16);
            const size_t ea = (size_t)(bm + r)*DM + kc*32 + c*8;
            const size_t eb = (size_t)(bn + r)*DM + kc*32 + c*8;
            cp_async16(base +              so, g_xhi + ea);
            cp_async16(base +   MAT_BYTES + so, g_xlo + ea);
            cp_async16(base + 2*MAT_BYTES + so, g_wt  + eb);
        }
        CP_COMMIT();
    };

    load_chunk(0, 0);

    for (int kc = 0; kc < 32; ++kc) {
        const int b = kc & 1;
        if (kc < 31) { load_chunk(kc + 1, b ^ 1); CP_WAIT(1); }
        else         { CP_WAIT(0); }
        __syncthreads();

        const uint32_t abase = sbase + b*BUFB;
        const uint32_t bbase = abase + 2*MAT_BYTES;

        #pragma unroll
        for (int ks = 0; ks < 2; ++ks) {
            const uint32_t colB = (uint32_t)(ks*32 + (lane >> 4)*16);

            uint32_t ahi[4][4], alo[4][4];
            #pragma unroll
            for (int i = 0; i < 4; ++i) {
                const uint32_t ad = abase +
                    (uint32_t)((wm*64 + i*16 + (lane & 15))*80) + colB;
                ldsm_x4(ahi[i], ad);
                ldsm_x4(alo[i], ad + MAT_BYTES);
            }
            uint32_t bq[4][2];
            #pragma unroll
            for (int jp = 0; jp < 2; ++jp) {
                uint32_t r4[4];
                const uint32_t bd = bbase +
                    (uint32_t)((wn*32 + jp*16 + (lane & 15))*80) + colB;
                ldsm_x4(r4, bd);
                bq[2*jp+0][0] = r4[0]; bq[2*jp+0][1] = r4[2];
                bq[2*jp+1][0] = r4[1]; bq[2*jp+1][1] = r4[3];
            }
            #pragma unroll
            for (int i = 0; i < 4; ++i)
                #pragma unroll
                for (int j = 0; j < 4; ++j) {
                    mma16816(acc[i][j], ahi[i], bq[j][0], bq[j][1]);
                    mma16816(acc[i][j], alo[i], bq[j][0], bq[j][1]);
                }
        }
        __syncthreads();
    }

    // ---- epilogue
    //  dst 0: Q -> g_qhi/g_qlo fp16 split (unscaled; 1/8 applied at score time)
    //  dst 1: K -> g_kh single fp16
    //  dst 2: V -> g_v fp32
    //  dst 3: plain fp32 row-major (final output)
    const int tg = lane >> 2;
    const int t4 = lane & 3;
    #pragma unroll
    for (int i = 0; i < 4; ++i) {
        #pragma unroll
        for (int j = 0; j < 4; ++j) {
            const int m0 = bm + wm*64 + i*16 + tg;
            const int n0 = bn + wn*32 + j*8 + t4*2;
            #pragma unroll
            for (int half = 0; half < 2; ++half) {
                const int m = m0 + half*8;
                const float x = acc[i][j][half*2+0];
                const float y = acc[i][j][half*2+1];
                if (dst_sel <= 1) {
                    const int bb = m >> 11, s = m & (SS-1);
                    const int h  = n0 >> 6, d = n0 & (DH-1);
                    const size_t oi = ((size_t)((bb << 4) + h) * SS + s) * DH + d;
                    __half hx = __float2half_rn(x);
                    __half hy = __float2half_rn(y);
                    if (dst_sel == 0) {
                        *(__half2*)&g_qhi[oi] = __half2(hx, hy);
                        *(__half2*)&g_qlo[oi] = __half2(
                            __float2half_rn(x - __half2float(hx)),
                            __float2half_rn(y - __half2float(hy)));
                    } else {
                        *(__half2*)&g_kh[oi] = __half2(hx, hy);
                    }
                } else if (dst_sel == 2) {
                    const int bb = m >> 11, s = m & (SS-1);
                    const int h  = n0 >> 6, d = n0 & (DH-1);
                    *(float2*)&g_v[((size_t)((bb << 4) + h) * SS + s) * DH + d] =
                        make_float2(x, y);
                } else {
                    *(float2*)&Yplain[(size_t)m * DM + n0] = make_float2(x, y);
                }
            }
        }
    }
}

// =============== V^T transpose + fp16: g_v -> g_vth [bh][dh][s] ===========
__global__ void vt_split_kernel()
{
    __shared__ float t[64][65];
    const int bh = blockIdx.y;
    const int sb = blockIdx.x << 6;
    const int tid = threadIdx.x;
    #pragma unroll
    for (int i = 0; i < 4; ++i) {
        const int f = tid + (i << 8);
        const int s = f >> 4, d4 = (f & 15) << 2;
        float4 v = *(const float4*)&g_v[((size_t)bh*SS + sb + s)*DH + d4];
        t[s][d4+0] = v.x; t[s][d4+1] = v.y; t[s][d4+2] = v.z; t[s][d4+3] = v.w;
    }
    __syncthreads();
    const int d  = tid >> 2;
    const int s0 = (tid & 3) << 4;
    #pragma unroll
    for (int j = 0; j < 16; j += 2) {
        const size_t oi = ((size_t)bh*DH + d)*SS + sb + s0 + j;
        *(__half2*)&g_vth[oi] = __half2(__float2half_rn(t[s0+j][d]),
                                        __float2half_rn(t[s0+j+1][d]));
    }
}

// =================== vmean: mean over S of V per (bh, d) ==================
__global__ void vmean_kernel()
{
    __shared__ float red[512];
    const int bh = blockIdx.x;
    const int d  = threadIdx.x & 63;
    const int sc = threadIdx.x >> 6;
    float acc = 0.f;
    const int base = (bh << 11) + (sc << 8);
    #pragma unroll 8
    for (int s = 0; s < 256; ++s)
        acc += g_v[(size_t)(base + s) * DH + d];
    red[threadIdx.x] = acc;
    __syncthreads();
    if (sc == 0) {
        float t = 0.f;
        #pragma unroll
        for (int j = 0; j < 8; ++j) t += red[(j << 6) + d];
        g_vmean[(bh << 6) + d] = t * (1.0f/2048.0f);
    }
}

// =================== HMMA flash attention (fp16 2-pass) ===================
// CTA = (bh, q-tile of 64 rows), 128 threads = 4 warps; warp w owns rows
// w*16..w*16+15. Scores: (qhi+qlo).k (k single fp16), scaled by 1/8 AFTER
// the mma; PV: (phi+plo).v (v single fp16).
#define ATT_ROWB 144                 // smem row stride (64 fp16 = 128B + 16 pad)
#define ATT_MATB (64*ATT_ROWB)       // 9216 per matrix
#define ATT_QHI  0
#define ATT_QLO  ATT_MATB
#define ATT_KV(b) (2*ATT_MATB + (b)*2*ATT_MATB)  // k, vt per buffer
#define ATT_KINI (2*ATT_MATB + 4*ATT_MATB)       // 55296
#define ATT_SMEM (ATT_KINI + 512)                // 55808

__global__ __launch_bounds__(128, 2)
void attn_kernel(const int* __restrict__ K_ini)
{
    extern __shared__ char attsm[];
    const uint32_t sb = smem_u32(attsm);
    const int tid  = threadIdx.x;
    const int lane = tid & 31;
    const int w    = tid >> 5;
    const int qt   = blockIdx.x;
    const int bh   = blockIdx.y;
    const int b    = bh >> 4;
    const int h    = bh & 15;

    const size_t qkbase = (size_t)bh * SS * DH;   // fp16 elems, [bh][s][dh]
    const size_t vtbase = (size_t)bh * DH * SS;   // [bh][dh][s]

    auto load_kv = [&](int kt, int bf) {
        const uint32_t kb = sb + ATT_KV(bf);
        #pragma unroll
        for (int i = 0; i < 4; ++i) {
            const int f = tid + (i << 7);
            const int r = f >> 3, c = f & 7;
            const uint32_t so = (uint32_t)(r*ATT_ROWB + c*16);
            const size_t gk = qkbase + (size_t)(kt*64 + r)*DH + c*8;
            const size_t gv = vtbase + (size_t)r*SS + kt*64 + c*8;
            cp_async16(kb +            so, g_kh  + gk);
            cp_async16(kb + ATT_MATB + so, g_vth + gv);
        }
        CP_COMMIT();
    };

    // ---- prologue: Q + K/V tile 0 (one cp.async group) + kini0
    #pragma unroll
    for (int i = 0; i < 4; ++i) {
        const int f = tid + (i << 7);
        const int r = f >> 3, c = f & 7;
        const uint32_t so = (uint32_t)(r*ATT_ROWB + c*16);
        const size_t gq = qkbase + (size_t)(qt*64 + r)*DH + c*8;
        cp_async16(sb + ATT_QHI + so, g_qhi + gq);
        cp_async16(sb + ATT_QLO + so, g_qlo + gq);
    }
    load_kv(0, 0);
    if (tid < 16)
        ((int4*)(attsm + ATT_KINI))[tid] =
            ((const int4*)(K_ini + b*SS))[tid];
    CP_WAIT(0);
    __syncthreads();

    // ---- Q A-fragments (resident)
    uint32_t qhi[4][4], qlo[4][4];
    const uint32_t lrow16 = (uint32_t)((lane & 15) * ATT_ROWB);
    const uint32_t lcol   = (uint32_t)((lane >> 4) << 4);
    #pragma unroll
    for (int kd = 0; kd < 4; ++kd) {
        const uint32_t qa = sb + (uint32_t)(w*16*ATT_ROWB) + lrow16 + kd*32 + lcol;
        ldsm_x4(qhi[kd], qa + ATT_QHI);
        ldsm_x4(qlo[kd], qa + ATT_QLO);
    }

    float o[8][4];
    #pragma unroll
    for (int jd = 0; jd < 8; ++jd)
        #pragma unroll
        for (int e = 0; e < 4; ++e) o[jd][e] = 0.f;
    float mrow[2] = {-3.0e38f, -3.0e38f};
    float lrow[2] = {0.f, 0.f};

    const int qr_loc = w*16 + (lane >> 2);   // tile-local row (half0)

    for (int kt = 0; kt <= qt; ++kt) {
        const int buf = kt & 1;
        if (kt < qt) { load_kv(kt + 1, buf ^ 1); CP_WAIT(1); }
        else         { CP_WAIT(0); }
        __syncthreads();
        if (kt < qt && tid < 16)
            ((int4*)(attsm + ATT_KINI))[(buf ^ 1)*16 + tid] =
                ((const int4*)(K_ini + b*SS + (kt + 1)*64))[tid];

        // ---- scores S = Q.K^T (2-pass: qhi, qlo vs single K)
        float s[8][4];
        #pragma unroll
        for (int jn = 0; jn < 8; ++jn)
            #pragma unroll
            for (int e = 0; e < 4; ++e) s[jn][e] = 0.f;

        const uint32_t kb = sb + ATT_KV(buf);
        #pragma unroll
        for (int nk = 0; nk < 4; ++nk) {
            #pragma unroll
            for (int kd = 0; kd < 4; ++kd) {
                uint32_t kf[4];
                const uint32_t ad = kb + (uint32_t)(nk*16*ATT_ROWB) + lrow16
                                  + kd*32 + lcol;
                ldsm_x4(kf, ad);
                mma16816(s[nk*2+0], qhi[kd], kf[0], kf[2]);
                mma16816(s[nk*2+0], qlo[kd], kf[0], kf[2]);
                mma16816(s[nk*2+1], qhi[kd], kf[1], kf[3]);
                mma16816(s[nk*2+1], qlo[kd], kf[1], kf[3]);
            }
        }

        // ---- scale by 1/sqrt(64), mask (pad + causal on diag), tile max
        const int* kini = (const int*)(attsm + ATT_KINI) + buf*64;
        const int diag = (kt == qt);
        float tmax[2] = {-3.0e38f, -3.0e38f};
        #pragma unroll
        for (int jn = 0; jn < 8; ++jn) {
            #pragma unroll
            for (int e = 0; e < 4; ++e) {
                const int col  = jn*8 + ((lane & 3) << 1) + (e & 1);
                const int half = e >> 1;
                bool masked = (kini[col] == 0);
                if (diag) masked = masked || (col > qr_loc + half*8);
                float sv = s[jn][e] * 0.125f;
                if (masked) sv -= NEG_BIG;       // exact -1e10 (fp32 absorb)
                s[jn][e] = sv;
                tmax[half] = fmaxf(tmax[half], sv);
            }
        }
        #pragma unroll
        for (int half = 0; half < 2; ++half) {
            tmax[half] = fmaxf(tmax[half], __shfl_xor_sync(0xffffffffu, tmax[half], 1));
            tmax[half] = fmaxf(tmax[half], __shfl_xor_sync(0xffffffffu, tmax[half], 2));
        }
        const float nm0 = fmaxf(mrow[0], tmax[0]);
        const float nm1 = fmaxf(mrow[1], tmax[1]);
        const float sc0 = __expf(mrow[0] - nm0);
        const float sc1 = __expf(mrow[1] - nm1);
        mrow[0] = nm0; mrow[1] = nm1;

        // ---- exp + P split into A-frags (register-only)
        uint32_t aphi[4][4], aplo[4][4];
        float ls0 = 0.f, ls1 = 0.f;
        #pragma unroll
        for (int jn = 0; jn < 8; ++jn) {
            const float p0 = __expf(s[jn][0] - nm0);
            const float p1 = __expf(s[jn][1] - nm0);
            const float p2 = __expf(s[jn][2] - nm1);
            const float p3 = __expf(s[jn][3] - nm1);
            ls0 += p0 + p1; ls1 += p2 + p3;
            __half h0 = __float2half_rn(p0);
            __half h1 = __float2half_rn(p1);
            __half h2 = __float2half_rn(p2);
            __half h3 = __float2half_rn(p3);
            const int kp  = jn >> 1;
            const int sub = (jn & 1) << 1;
            aphi[kp][sub+0] = pk2(h0, h1);
            aphi[kp][sub+1] = pk2(h2, h3);
            aplo[kp][sub+0] = pk2(__float2half_rn(p0 - __half2float(h0)),
                                  __float2half_rn(p1 - __half2float(h1)));
            aplo[kp][sub+1] = pk2(__float2half_rn(p2 - __half2float(h2)),
                                  __float2half_rn(p3 - __half2float(h3)));
        }
        ls0 += __shfl_xor_sync(0xffffffffu, ls0, 1);
        ls0 += __shfl_xor_sync(0xffffffffu, ls0, 2);
        ls1 += __shfl_xor_sync(0xffffffffu, ls1, 1);
        ls1 += __shfl_xor_sync(0xffffffffu, ls1, 2);
        lrow[0] = lrow[0]*sc0 + ls0;
        lrow[1] = lrow[1]*sc1 + ls1;
        #pragma unroll
        for (int jd = 0; jd < 8; ++jd) {
            o[jd][0] *= sc0; o[jd][1] *= sc0;
            o[jd][2] *= sc1; o[jd][3] *= sc1;
        }

        // ---- O += P.V (2-pass: phi, plo vs single V^T)
        const uint32_t vb = kb + ATT_MATB;
        #pragma unroll
        for (int nd = 0; nd < 4; ++nd) {
            #pragma unroll
            for (int kp = 0; kp < 4; ++kp) {
                uint32_t vf[4];
                const uint32_t ad = vb + (uint32_t)(nd*16*ATT_ROWB) + lrow16
                                  + kp*32 + lcol;
                ldsm_x4(vf, ad);
                mma16816(o[nd*2+0], aphi[kp], vf[0], vf[2]);
                mma16816(o[nd*2+0], aplo[kp], vf[0], vf[2]);
                mma16816(o[nd*2+1], aphi[kp], vf[1], vf[3]);
                mma16816(o[nd*2+1], aplo[kp], vf[1], vf[3]);
            }
        }
        __syncthreads();   // protect buf reuse by next iteration's prefetch
    }

    // ---- epilogue: ctx fp16 hi/lo split straight into the WO-GEMM input
    #pragma unroll
    for (int half = 0; half < 2; ++half) {
        const int row = qr_loc + half*8;
        const size_t mg = (size_t)(b*SS + qt*64 + row);
        const float inv = 1.0f / lrow[half];
        const bool fullmask = (mrow[half] < -1e9f);  // all-visible-masked row
        #pragma unroll
        for (int jd = 0; jd < 8; ++jd) {
            const int d = jd*8 + ((lane & 3) << 1);
            float v0, v1;
            if (fullmask) {
                // reference: all scores exactly -1e10 -> uniform softmax over
                // ALL 2048 keys -> mean of V
                v0 = g_vmean[bh*64 + d];
                v1 = g_vmean[bh*64 + d + 1];
            } else {
                v0 = o[jd][half*2+0] * inv;
                v1 = o[jd][half*2+1] * inv;
            }
            __half h0 = __float2half_rn(v0);
            __half h1 = __float2half_rn(v1);
            const size_t oi = mg*DM + h*64 + d;
            *(__half2*)&g_xhi[oi] = __half2(h0, h1);
            *(__half2*)&g_xlo[oi] = __half2(
                __float2half_rn(v0 - __half2float(h0)),
                __float2half_rn(v1 - __half2float(h1)));
        }
    }
}

// ============================ launch ======================================
extern "C" void kernel_launch(void* const* d_in, const int* in_sizes, int n_in,
                              void* d_out, int out_size)
{
    const float* Q_emb = (const float*)d_in[0];
    const float* K_emb = (const float*)d_in[1];
    const float* V_emb = (const float*)d_in[2];
    const int*   K_ini = (const int*)  d_in[4];
    const float* WQ    = (const float*)d_in[5];
    const float* WK    = (const float*)d_in[6];
    const float* WV    = (const float*)d_in[7];
    const float* WO    = (const float*)d_in[8];
    float* out = (float*)d_out;
    (void)in_sizes; (void)n_in; (void)out_size;

    cudaFuncSetAttribute(mma_gemm_kernel,
                         cudaFuncAttributeMaxDynamicSharedMemorySize, GEMM_SMEM);
    cudaFuncSetAttribute(attn_kernel,
                         cudaFuncAttributeMaxDynamicSharedMemorySize, ATT_SMEM);

    const dim3 gg(DM/128, MM/128);          // (8, 64)
    const int convx_blocks = (MM*DM/4)/256; // 8192
    const int convw_blocks = (DM*256)/256;  // 1024

    conv_w_kernel<<<convw_blocks, 256>>>(WQ);
    conv_x_kernel<<<convx_blocks, 256>>>(Q_emb);
    mma_gemm_kernel<<<gg, 256, GEMM_SMEM>>>(nullptr, 0);   // -> Q fp16 split

    conv_w_kernel<<<convw_blocks, 256>>>(WK);
    conv_x_kernel<<<convx_blocks, 256>>>(K_emb);
    mma_gemm_kernel<<<gg, 256, GEMM_SMEM>>>(nullptr, 1);   // -> K fp16

    conv_w_kernel<<<convw_blocks, 256>>>(WV);
    conv_x_kernel<<<convx_blocks, 256>>>(V_emb);
    mma_gemm_kernel<<<gg, 256, GEMM_SMEM>>>(nullptr, 2);   // -> g_v fp32

    vt_split_kernel<<<dim3(SS/64, BB*HH), 256>>>();        // -> V^T fp16
    vmean_kernel<<<BB*HH, 512>>>();

    attn_kernel<<<dim3(SS/64, BB*HH), 128, ATT_SMEM>>>(K_ini); // -> ctx split

    conv_w_kernel<<<convw_blocks, 256>>>(WO);
    mma_gemm_kernel<<<gg, 256, GEMM_SMEM>>>(out, 3);       // ctx @ WO -> out
}

// round 13
// speedup vs baseline: 9.0112x; 1.1348x over previous
#include <cuda_runtime.h>
#include <cuda_fp16.h>
#include <cstdint>

// Problem constants
// B=4, S=2048, H=16, dh=64, D=1024, M = B*S = 8192
// Inputs: 0 Q_emb f32  1 K_emb f32  2 V_emb f32  3 Q_ini i32 (unused)
//         4 K_ini i32  5 WQ  6 WK  7 WV  8 WO (all f32 [1024,1024])
// Output: f32 [B,S,D]
//
// compute_103 virtual arch: no tcgen05. Tensor path (validated R10-R12):
// cp.async + ldmatrix + mma.sync.m16n8k16.f16, asymmetric fp16 2-pass:
//   X@W   ~= (Xhi+Xlo)@fp16(W)
//   Q.K^T ~= (Qhi+Qlo).fp16(K)^T   (1/8 scale applied post-mma)
//   P.V   ~= (Phi+Plo).fp16(V)

#define BB   4
#define SS   2048
#define HH   16
#define DH   64
#define DM   1024
#define MM   (BB*SS)          // 8192
#define NEG_BIG 1e10f

// ---------------- scratch (device globals; no allocations allowed) --------
__device__ float g_v[BB*HH*SS*DH];        // [BH,S,dh] fp32
__device__ float g_vmean[BB*HH*DH];       // [BH,dh]
__device__ __half g_qhi[BB*HH*SS*DH];     // Q split (unscaled), [bh][s][dh]
__device__ __half g_qlo[BB*HH*SS*DH];
__device__ __half g_kh [BB*HH*SS*DH];     // K single fp16, [bh][s][dh]
__device__ __half g_vth[BB*HH*SS*DH];     // V^T single fp16, [bh][dh][s]
__device__ __half g_x_hi[3][MM*DM];       // X splits: slots 0/1/2 = Q/K/V emb
__device__ __half g_x_lo[3][MM*DM];       //  (slot 0 reused for ctx -> WO)
__device__ __half g_wt4[4][DM*DM];        // W^T fp16 [N][K]: WQ,WK,WV,WO

// ======================= inline PTX helpers (compute_103-safe) ============
__device__ __forceinline__ uint32_t smem_u32(const void* p) {
    uint32_t a;
    asm("{ .reg .u64 t; cvta.to.shared.u64 t, %1; cvt.u32.u64 %0, t; }"
        : "=r"(a) : "l"(p));
    return a;
}
__device__ __forceinline__ void cp_async16(uint32_t dst, const void* src) {
    asm volatile("cp.async.cg.shared.global [%0], [%1], 16;"
                 :: "r"(dst), "l"(src) : "memory");
}
#define CP_COMMIT()  asm volatile("cp.async.commit_group;" ::: "memory")
#define CP_WAIT(n)   asm volatile("cp.async.wait_group %0;" :: "n"(n) : "memory")

__device__ __forceinline__ void ldsm_x4(uint32_t r[4], uint32_t addr) {
    asm volatile("ldmatrix.sync.aligned.m8n8.x4.shared.b16 {%0,%1,%2,%3}, [%4];"
                 : "=r"(r[0]), "=r"(r[1]), "=r"(r[2]), "=r"(r[3]) : "r"(addr));
}
__device__ __forceinline__ void mma16816(float c[4], const uint32_t a[4],
                                         uint32_t b0, uint32_t b1) {
    asm volatile(
        "mma.sync.aligned.m16n8k16.row.col.f32.f16.f16.f32 "
        "{%0,%1,%2,%3}, {%4,%5,%6,%7}, {%8,%9}, {%0,%1,%2,%3};"
        : "+f"(c[0]), "+f"(c[1]), "+f"(c[2]), "+f"(c[3])
        : "r"(a[0]), "r"(a[1]), "r"(a[2]), "r"(a[3]), "r"(b0), "r"(b1));
}
__device__ __forceinline__ uint32_t pk2(__half lo, __half hi) {
    __half2 v(lo, hi);
    return *(uint32_t*)&v;
}

// ======================= fused split-conversion kernels ===================
// grid (8192, 3): y selects Q/K/V embedding -> g_x_hi/lo[y]
__global__ void conv_x_kernel(const float* __restrict__ q,
                              const float* __restrict__ k,
                              const float* __restrict__ v)
{
    const int z = blockIdx.y;
    const float* X = (z == 0) ? q : (z == 1) ? k : v;
    __half* dh = g_x_hi[z];
    __half* dl = g_x_lo[z];
    const size_t idx = (size_t)blockIdx.x * blockDim.x + threadIdx.x; // float4
    float4 vv = ((const float4*)X)[idx];
    float f[4] = {vv.x, vv.y, vv.z, vv.w};
    __half h[4], l[4];
    #pragma unroll
    for (int i = 0; i < 4; ++i) {
        h[i] = __float2half_rn(f[i]);
        l[i] = __float2half_rn(f[i] - __half2float(h[i]));
    }
    ((__half2*)dh)[idx*2+0] = __half2(h[0], h[1]);
    ((__half2*)dh)[idx*2+1] = __half2(h[2], h[3]);
    ((__half2*)dl)[idx*2+0] = __half2(l[0], l[1]);
    ((__half2*)dl)[idx*2+1] = __half2(l[2], l[3]);
}

// grid (1024, 4): y selects WQ/WK/WV/WO; W f32 [K,N] -> W^T fp16 [N,K]
__global__ void conv_w_kernel(const float* __restrict__ wq,
                              const float* __restrict__ wk,
                              const float* __restrict__ wv,
                              const float* __restrict__ wo)
{
    const int z = blockIdx.y;
    const float* W = (z == 0) ? wq : (z == 1) ? wk : (z == 2) ? wv : wo;
    __half* dst = g_wt4[z];
    const int idx = blockIdx.x * blockDim.x + threadIdx.x;
    const int n  = idx >> 8;
    const int kq = (idx & 255) << 2;
    __half h[4];
    #pragma unroll
    for (int j = 0; j < 4; ++j)
        h[j] = __float2half_rn(W[(size_t)(kq + j) * DM + n]);
    const size_t o2 = ((size_t)n * DM + kq) >> 1;
    ((__half2*)dst)[o2+0] = __half2(h[0], h[1]);
    ((__half2*)dst)[o2+1] = __half2(h[2], h[3]);
}

// ============== HMMA GEMM: C[8192,1024] = X @ W (fp16 2-pass) =============
// blockIdx.z selects (X slot, W slot, dst) = (xsel+z, wsel+z, dsel+z), so
// the QKV projections run as ONE launch with grid.z=3.
#define MAT_BYTES (128*80)            // 10240 B
#define BUFB      (3*MAT_BYTES)       // Xhi, Xlo, Wt = 30720 B
#define GEMM_SMEM (2*BUFB)            // 61440 B

__global__ __launch_bounds__(256, 1)
void mma_gemm_kernel(float* __restrict__ Yplain, int xsel, int wsel, int dsel)
{
    extern __shared__ char smg[];
    const int tid  = threadIdx.x;
    const int lane = tid & 31;
    const int wid  = tid >> 5;
    const int wm   = wid >> 2;
    const int wn   = wid & 3;
    const int bm   = blockIdx.y * 128;
    const int bn   = blockIdx.x * 128;
    const uint32_t sbase = smem_u32(smg);

    const int z = blockIdx.z;
    const __half* Xh = g_x_hi[xsel + z];
    const __half* Xl = g_x_lo[xsel + z];
    const __half* Wt = g_wt4 [wsel + z];
    const int dst_sel = dsel + z;

    float acc[4][4][4];
    #pragma unroll
    for (int i = 0; i < 4; ++i)
        #pragma unroll
        for (int j = 0; j < 4; ++j)
            #pragma unroll
            for (int t = 0; t < 4; ++t) acc[i][j][t] = 0.f;

    auto load_chunk = [&](int kc, int b) {
        const uint32_t base = sbase + b*BUFB;
        #pragma unroll
        for (int t = 0; t < 2; ++t) {
            const int idx = tid + (t << 8);
            const int r = idx >> 2, c = idx & 3;
            const uint32_t so = (uint32_t)(r*80 + c*16);
            const size_t ea = (size_t)(bm + r)*DM + kc*32 + c*8;
            const size_t eb = (size_t)(bn + r)*DM + kc*32 + c*8;
            cp_async16(base +              so, Xh + ea);
            cp_async16(base +   MAT_BYTES + so, Xl + ea);
            cp_async16(base + 2*MAT_BYTES + so, Wt + eb);
        }
        CP_COMMIT();
    };

    load_chunk(0, 0);

    for (int kc = 0; kc < 32; ++kc) {
        const int b = kc & 1;
        if (kc < 31) { load_chunk(kc + 1, b ^ 1); CP_WAIT(1); }
        else         { CP_WAIT(0); }
        __syncthreads();

        const uint32_t abase = sbase + b*BUFB;
        const uint32_t bbase = abase + 2*MAT_BYTES;

        #pragma unroll
        for (int ks = 0; ks < 2; ++ks) {
            const uint32_t colB = (uint32_t)(ks*32 + (lane >> 4)*16);

            uint32_t ahi[4][4], alo[4][4];
            #pragma unroll
            for (int i = 0; i < 4; ++i) {
                const uint32_t ad = abase +
                    (uint32_t)((wm*64 + i*16 + (lane & 15))*80) + colB;
                ldsm_x4(ahi[i], ad);
                ldsm_x4(alo[i], ad + MAT_BYTES);
            }
            uint32_t bq[4][2];
            #pragma unroll
            for (int jp = 0; jp < 2; ++jp) {
                uint32_t r4[4];
                const uint32_t bd = bbase +
                    (uint32_t)((wn*32 + jp*16 + (lane & 15))*80) + colB;
                ldsm_x4(r4, bd);
                bq[2*jp+0][0] = r4[0]; bq[2*jp+0][1] = r4[2];
                bq[2*jp+1][0] = r4[1]; bq[2*jp+1][1] = r4[3];
            }
            #pragma unroll
            for (int i = 0; i < 4; ++i)
                #pragma unroll
                for (int j = 0; j < 4; ++j) {
                    mma16816(acc[i][j], ahi[i], bq[j][0], bq[j][1]);
                    mma16816(acc[i][j], alo[i], bq[j][0], bq[j][1]);
                }
        }
        __syncthreads();
    }

    // ---- epilogue: 0=Q split, 1=K fp16, 2=V fp32, 3=plain fp32
    const int tg = lane >> 2;
    const int t4 = lane & 3;
    #pragma unroll
    for (int i = 0; i < 4; ++i) {
        #pragma unroll
        for (int j = 0; j < 4; ++j) {
            const int m0 = bm + wm*64 + i*16 + tg;
            const int n0 = bn + wn*32 + j*8 + t4*2;
            #pragma unroll
            for (int half = 0; half < 2; ++half) {
                const int m = m0 + half*8;
                const float x = acc[i][j][half*2+0];
                const float y = acc[i][j][half*2+1];
                if (dst_sel <= 1) {
                    const int bb = m >> 11, s = m & (SS-1);
                    const int h  = n0 >> 6, d = n0 & (DH-1);
                    const size_t oi = ((size_t)((bb << 4) + h) * SS + s) * DH + d;
                    __half hx = __float2half_rn(x);
                    __half hy = __float2half_rn(y);
                    if (dst_sel == 0) {
                        *(__half2*)&g_qhi[oi] = __half2(hx, hy);
                        *(__half2*)&g_qlo[oi] = __half2(
                            __float2half_rn(x - __half2float(hx)),
                            __float2half_rn(y - __half2float(hy)));
                    } else {
                        *(__half2*)&g_kh[oi] = __half2(hx, hy);
                    }
                } else if (dst_sel == 2) {
                    const int bb = m >> 11, s = m & (SS-1);
                    const int h  = n0 >> 6, d = n0 & (DH-1);
                    *(float2*)&g_v[((size_t)((bb << 4) + h) * SS + s) * DH + d] =
                        make_float2(x, y);
                } else {
                    *(float2*)&Yplain[(size_t)m * DM + n0] = make_float2(x, y);
                }
            }
        }
    }
}

// =============== V^T transpose + fp16: g_v -> g_vth [bh][dh][s] ===========
__global__ void vt_split_kernel()
{
    __shared__ float t[64][65];
    const int bh = blockIdx.y;
    const int sb = blockIdx.x << 6;
    const int tid = threadIdx.x;
    #pragma unroll
    for (int i = 0; i < 4; ++i) {
        const int f = tid + (i << 8);
        const int s = f >> 4, d4 = (f & 15) << 2;
        float4 v = *(const float4*)&g_v[((size_t)bh*SS + sb + s)*DH + d4];
        t[s][d4+0] = v.x; t[s][d4+1] = v.y; t[s][d4+2] = v.z; t[s][d4+3] = v.w;
    }
    __syncthreads();
    const int d  = tid >> 2;
    const int s0 = (tid & 3) << 4;
    #pragma unroll
    for (int j = 0; j < 16; j += 2) {
        const size_t oi = ((size_t)bh*DH + d)*SS + sb + s0 + j;
        *(__half2*)&g_vth[oi] = __half2(__float2half_rn(t[s0+j][d]),
                                        __float2half_rn(t[s0+j+1][d]));
    }
}

// =================== vmean: mean over S of V per (bh, d) ==================
__global__ void vmean_kernel()
{
    __shared__ float red[512];
    const int bh = blockIdx.x;
    const int d  = threadIdx.x & 63;
    const int sc = threadIdx.x >> 6;
    float acc = 0.f;
    const int base = (bh << 11) + (sc << 8);
    #pragma unroll 8
    for (int s = 0; s < 256; ++s)
        acc += g_v[(size_t)(base + s) * DH + d];
    red[threadIdx.x] = acc;
    __syncthreads();
    if (sc == 0) {
        float t = 0.f;
        #pragma unroll
        for (int j = 0; j < 8; ++j) t += red[(j << 6) + d];
        g_vmean[(bh << 6) + d] = t * (1.0f/2048.0f);
    }
}

// =================== HMMA flash attention (fp16 2-pass) ===================
// CTA = (bh, q-tile of 128 rows), 256 threads = 8 warps; warp w owns rows
// w*16..w*16+15. K/V tiles of 64 keys, double-buffered. Tile-iters per bh
// drop 528 -> 272 vs the 64-row version (half the K/V traffic + barriers).
#define ATT_ROWB  144                 // smem row stride (128 B + 16 pad)
#define ATT_KMATB (64*ATT_ROWB)       // 9216  (K or V^T tile)
#define ATT_QMATB (128*ATT_ROWB)      // 18432 (Q tile)
#define ATT_QHI   0
#define ATT_QLO   ATT_QMATB
#define ATT_KV(b) (2*ATT_QMATB + (b)*2*ATT_KMATB)
#define ATT_KINI  (2*ATT_QMATB + 4*ATT_KMATB)   // 73728
#define ATT_SMEM  (ATT_KINI + 512)              // 74240

__global__ __launch_bounds__(256, 1)
void attn_kernel(const int* __restrict__ K_ini)
{
    extern __shared__ char attsm[];
    const uint32_t sb = smem_u32(attsm);
    const int tid  = threadIdx.x;
    const int lane = tid & 31;
    const int w    = tid >> 5;                 // 0..7
    const int qt   = (SS/128 - 1) - blockIdx.x; // longest CTAs first
    const int bh   = blockIdx.y;
    const int b    = bh >> 4;
    const int h    = bh & 15;

    const size_t qkbase = (size_t)bh * SS * DH;   // [bh][s][dh]
    const size_t vtbase = (size_t)bh * DH * SS;   // [bh][dh][s]

    auto load_kv = [&](int kt, int bf) {
        const uint32_t kb = sb + ATT_KV(bf);
        #pragma unroll
        for (int i = 0; i < 2; ++i) {
            const int f = tid + (i << 8);
            const int r = f >> 3, c = f & 7;     // r 0..63
            const uint32_t so = (uint32_t)(r*ATT_ROWB + c*16);
            const size_t gk = qkbase + (size_t)(kt*64 + r)*DH + c*8;
            const size_t gv = vtbase + (size_t)r*SS + kt*64 + c*8;
            cp_async16(kb +             so, g_kh  + gk);
            cp_async16(kb + ATT_KMATB + so, g_vth + gv);
        }
        CP_COMMIT();
    };

    // ---- prologue: Q (128 rows, hi+lo) + K/V tile 0 + kini0
    #pragma unroll
    for (int i = 0; i < 4; ++i) {
        const int f = tid + (i << 8);
        const int r = f >> 3, c = f & 7;         // r 0..127
        const uint32_t so = (uint32_t)(r*ATT_ROWB + c*16);
        const size_t gq = qkbase + (size_t)(qt*128 + r)*DH + c*8;
        cp_async16(sb + ATT_QHI + so, g_qhi + gq);
        cp_async16(sb + ATT_QLO + so, g_qlo + gq);
    }
    load_kv(0, 0);
    if (tid < 16)
        ((int4*)(attsm + ATT_KINI))[tid] = ((const int4*)(K_ini + b*SS))[tid];
    CP_WAIT(0);
    __syncthreads();

    // ---- Q A-fragments (resident)
    uint32_t qhi[4][4], qlo[4][4];
    const uint32_t lrow16 = (uint32_t)((lane & 15) * ATT_ROWB);
    const uint32_t lcol   = (uint32_t)((lane >> 4) << 4);
    #pragma unroll
    for (int kd = 0; kd < 4; ++kd) {
        const uint32_t qa = sb + (uint32_t)(w*16*ATT_ROWB) + lrow16 + kd*32 + lcol;
        ldsm_x4(qhi[kd], qa + ATT_QHI);
        ldsm_x4(qlo[kd], qa + ATT_QLO);
    }

    float o[8][4];
    #pragma unroll
    for (int jd = 0; jd < 8; ++jd)
        #pragma unroll
        for (int e = 0; e < 4; ++e) o[jd][e] = 0.f;
    float mrow[2] = {-3.0e38f, -3.0e38f};
    float lrow[2] = {0.f, 0.f};

    const int qr_loc = w*16 + (lane >> 2);     // tile-local row (half0), 0..127
    const int ktmax  = 2*qt + 1;

    for (int kt = 0; kt <= ktmax; ++kt) {
        const int buf = kt & 1;
        if (kt < ktmax) { load_kv(kt + 1, buf ^ 1); CP_WAIT(1); }
        else            { CP_WAIT(0); }
        __syncthreads();
        if (kt < ktmax && tid < 16)
            ((int4*)(attsm + ATT_KINI))[(buf ^ 1)*16 + tid] =
                ((const int4*)(K_ini + b*SS + (kt + 1)*64))[tid];

        // ---- scores S = Q.K^T (2-pass: qhi, qlo vs single K)
        float s[8][4];
        #pragma unroll
        for (int jn = 0; jn < 8; ++jn)
            #pragma unroll
            for (int e = 0; e < 4; ++e) s[jn][e] = 0.f;

        const uint32_t kb = sb + ATT_KV(buf);
        #pragma unroll
        for (int nk = 0; nk < 4; ++nk) {
            #pragma unroll
            for (int kd = 0; kd < 4; ++kd) {
                uint32_t kf[4];
                const uint32_t ad = kb + (uint32_t)(nk*16*ATT_ROWB) + lrow16
                                  + kd*32 + lcol;
                ldsm_x4(kf, ad);
                mma16816(s[nk*2+0], qhi[kd], kf[0], kf[2]);
                mma16816(s[nk*2+0], qlo[kd], kf[0], kf[2]);
                mma16816(s[nk*2+1], qhi[kd], kf[1], kf[3]);
                mma16816(s[nk*2+1], qlo[kd], kf[1], kf[3]);
            }
        }

        // ---- scale 1/8, mask (pad + causal on the last two tiles), tile max
        const int* kini = (const int*)(attsm + ATT_KINI) + buf*64;
        const int needc = (kt >= 2*qt);   // only tiles overlapping the diagonal
        float tmax[2] = {-3.0e38f, -3.0e38f};
        #pragma unroll
        for (int jn = 0; jn < 8; ++jn) {
            #pragma unroll
            for (int e = 0; e < 4; ++e) {
                const int col  = jn*8 + ((lane & 3) << 1) + (e & 1);
                const int half = e >> 1;
                bool masked = (kini[col] == 0);
                if (needc) masked = masked || (kt*64 + col > qt*128 + qr_loc + half*8);
                float sv = s[jn][e] * 0.125f;
                if (masked) sv -= NEG_BIG;       // exact -1e10 (fp32 absorb)
                s[jn][e] = sv;
                tmax[half] = fmaxf(tmax[half], sv);
            }
        }
        #pragma unroll
        for (int half = 0; half < 2; ++half) {
            tmax[half] = fmaxf(tmax[half], __shfl_xor_sync(0xffffffffu, tmax[half], 1));
            tmax[half] = fmaxf(tmax[half], __shfl_xor_sync(0xffffffffu, tmax[half], 2));
        }
        const float nm0 = fmaxf(mrow[0], tmax[0]);
        const float nm1 = fmaxf(mrow[1], tmax[1]);
        const float sc0 = __expf(mrow[0] - nm0);
        const float sc1 = __expf(mrow[1] - nm1);
        mrow[0] = nm0; mrow[1] = nm1;

        // ---- exp + P split into A-frags (register-only)
        uint32_t aphi[4][4], aplo[4][4];
        float ls0 = 0.f, ls1 = 0.f;
        #pragma unroll
        for (int jn = 0; jn < 8; ++jn) {
            const float p0 = __expf(s[jn][0] - nm0);
            const float p1 = __expf(s[jn][1] - nm0);
            const float p2 = __expf(s[jn][2] - nm1);
            const float p3 = __expf(s[jn][3] - nm1);
            ls0 += p0 + p1; ls1 += p2 + p3;
            __half h0 = __float2half_rn(p0);
            __half h1 = __float2half_rn(p1);
            __half h2 = __float2half_rn(p2);
            __half h3 = __float2half_rn(p3);
            const int kp  = jn >> 1;
            const int sub = (jn & 1) << 1;
            aphi[kp][sub+0] = pk2(h0, h1);
            aphi[kp][sub+1] = pk2(h2, h3);
            aplo[kp][sub+0] = pk2(__float2half_rn(p0 - __half2float(h0)),
                                  __float2half_rn(p1 - __half2float(h1)));
            aplo[kp][sub+1] = pk2(__float2half_rn(p2 - __half2float(h2)),
                                  __float2half_rn(p3 - __half2float(h3)));
        }
        ls0 += __shfl_xor_sync(0xffffffffu, ls0, 1);
        ls0 += __shfl_xor_sync(0xffffffffu, ls0, 2);
        ls1 += __shfl_xor_sync(0xffffffffu, ls1, 1);
        ls1 += __shfl_xor_sync(0xffffffffu, ls1, 2);
        lrow[0] = lrow[0]*sc0 + ls0;
        lrow[1] = lrow[1]*sc1 + ls1;
        #pragma unroll
        for (int jd = 0; jd < 8; ++jd) {
            o[jd][0] *= sc0; o[jd][1] *= sc0;
            o[jd][2] *= sc1; o[jd][3] *= sc1;
        }

        // ---- O += P.V (2-pass: phi, plo vs single V^T)
        const uint32_t vb = kb + ATT_KMATB;
        #pragma unroll
        for (int nd = 0; nd < 4; ++nd) {
            #pragma unroll
            for (int kp = 0; kp < 4; ++kp) {
                uint32_t vf[4];
                const uint32_t ad = vb + (uint32_t)(nd*16*ATT_ROWB) + lrow16
                                  + kp*32 + lcol;
                ldsm_x4(vf, ad);
                mma16816(o[nd*2+0], aphi[kp], vf[0], vf[2]);
                mma16816(o[nd*2+0], aplo[kp], vf[0], vf[2]);
                mma16816(o[nd*2+1], aphi[kp], vf[1], vf[3]);
                mma16816(o[nd*2+1], aplo[kp], vf[1], vf[3]);
            }
        }
        __syncthreads();   // protect buf reuse by next iteration's prefetch
    }

    // ---- epilogue: ctx fp16 hi/lo split into the WO-GEMM input (slot 0)
    #pragma unroll
    for (int half = 0; half < 2; ++half) {
        const int row = qr_loc + half*8;
        const size_t mg = (size_t)(b*SS + qt*128 + row);
        const float inv = 1.0f / lrow[half];
        const bool fullmask = (mrow[half] < -1e9f);
        #pragma unroll
        for (int jd = 0; jd < 8; ++jd) {
            const int d = jd*8 + ((lane & 3) << 1);
            float v0, v1;
            if (fullmask) {
                // reference: all scores exactly -1e10 -> uniform softmax over
                // ALL 2048 keys -> mean of V
                v0 = g_vmean[bh*64 + d];
                v1 = g_vmean[bh*64 + d + 1];
            } else {
                v0 = o[jd][half*2+0] * inv;
                v1 = o[jd][half*2+1] * inv;
            }
            __half h0 = __float2half_rn(v0);
            __half h1 = __float2half_rn(v1);
            const size_t oi = mg*DM + h*64 + d;
            *(__half2*)&g_x_hi[0][oi] = __half2(h0, h1);
            *(__half2*)&g_x_lo[0][oi] = __half2(
                __float2half_rn(v0 - __half2float(h0)),
                __float2half_rn(v1 - __half2float(h1)));
        }
    }
}

// ============================ launch ======================================
extern "C" void kernel_launch(void* const* d_in, const int* in_sizes, int n_in,
                              void* d_out, int out_size)
{
    const float* Q_emb = (const float*)d_in[0];
    const float* K_emb = (const float*)d_in[1];
    const float* V_emb = (const float*)d_in[2];
    const int*   K_ini = (const int*)  d_in[4];
    const float* WQ    = (const float*)d_in[5];
    const float* WK    = (const float*)d_in[6];
    const float* WV    = (const float*)d_in[7];
    const float* WO    = (const float*)d_in[8];
    float* out = (float*)d_out;
    (void)in_sizes; (void)n_in; (void)out_size;

    cudaFuncSetAttribute(mma_gemm_kernel,
                         cudaFuncAttributeMaxDynamicSharedMemorySize, GEMM_SMEM);
    cudaFuncSetAttribute(attn_kernel,
                         cudaFuncAttributeMaxDynamicSharedMemorySize, ATT_SMEM);

    // fused conversions (one launch each)
    conv_w_kernel<<<dim3((DM*256)/256, 4), 256>>>(WQ, WK, WV, WO);
    conv_x_kernel<<<dim3((MM*DM/4)/256, 3), 256>>>(Q_emb, K_emb, V_emb);

    // fused QKV projections: grid.z = 3 -> (X_z, W_z, dst_z)
    mma_gemm_kernel<<<dim3(DM/128, MM/128, 3), 256, GEMM_SMEM>>>(nullptr, 0, 0, 0);

    vt_split_kernel<<<dim3(SS/64, BB*HH), 256>>>();   // -> V^T fp16
    vmean_kernel<<<BB*HH, 512>>>();

    attn_kernel<<<dim3(SS/128, BB*HH), 256, ATT_SMEM>>>(K_ini); // -> ctx split

    // output projection: ctx (slot 0) @ WO -> out
    mma_gemm_kernel<<<dim3(DM/128, MM/128, 1), 256, GEMM_SMEM>>>(out, 0, 3, 3);
}

// round 14
// speedup vs baseline: 13.7621x; 1.5272x over previous
#include <cuda_runtime.h>
#include <cuda_fp16.h>
#include <cstdint>

// Problem constants
// B=4, S=2048, H=16, dh=64, D=1024, M = B*S = 8192
// Inputs: 0 Q_emb f32  1 K_emb f32  2 V_emb f32  3 Q_ini i32 (unused)
//         4 K_ini i32  5 WQ  6 WK  7 WV  8 WO (all f32 [1024,1024])
// Output: f32 [B,S,D]
//
// compute_103 virtual arch: no tcgen05. Tensor path: cp.async + ldmatrix +
// mma.sync.m16n8k16.f16 (layout validated R10-R13). This revision is
// single-pass fp16 on every stage (no hi/lo splits): measured R13 shows the
// pipeline is mma-issue-bound (rt_SMSP~16), so halving mma count is the
// only lever. Predicted rel_err ~6e-4 (per-site fp16 rounding ~1.6e-4 RMS,
// ~12 sites in quadrature), inside the 1e-3 gate.

#define BB   4
#define SS   2048
#define HH   16
#define DH   64
#define DM   1024
#define MM   (BB*SS)          // 8192
#define NEG_BIG 1e10f

// ---------------- scratch (device globals; no allocations allowed) --------
__device__ float g_v[BB*HH*SS*DH];        // [BH,S,dh] fp32
__device__ float g_vmean[BB*HH*DH];       // [BH,dh]
__device__ __half g_qh [BB*HH*SS*DH];     // Q fp16 (unscaled), [bh][s][dh]
__device__ __half g_kh [BB*HH*SS*DH];     // K fp16, [bh][s][dh]
__device__ __half g_vth[BB*HH*SS*DH];     // V^T fp16, [bh][dh][s]
__device__ __half g_x[3][MM*DM];          // X fp16: slots 0/1/2 = Q/K/V emb
                                          //  (slot 0 reused for ctx -> WO)
__device__ __half g_wt4[4][DM*DM];        // W^T fp16 [N][K]: WQ,WK,WV,WO

// ======================= inline PTX helpers (compute_103-safe) ============
__device__ __forceinline__ uint32_t smem_u32(const void* p) {
    uint32_t a;
    asm("{ .reg .u64 t; cvta.to.shared.u64 t, %1; cvt.u32.u64 %0, t; }"
        : "=r"(a) : "l"(p));
    return a;
}
__device__ __forceinline__ void cp_async16(uint32_t dst, const void* src) {
    asm volatile("cp.async.cg.shared.global [%0], [%1], 16;"
                 :: "r"(dst), "l"(src) : "memory");
}
#define CP_COMMIT()  asm volatile("cp.async.commit_group;" ::: "memory")
#define CP_WAIT(n)   asm volatile("cp.async.wait_group %0;" :: "n"(n) : "memory")

__device__ __forceinline__ void ldsm_x4(uint32_t r[4], uint32_t addr) {
    asm volatile("ldmatrix.sync.aligned.m8n8.x4.shared.b16 {%0,%1,%2,%3}, [%4];"
                 : "=r"(r[0]), "=r"(r[1]), "=r"(r[2]), "=r"(r[3]) : "r"(addr));
}
__device__ __forceinline__ void mma16816(float c[4], const uint32_t a[4],
                                         uint32_t b0, uint32_t b1) {
    asm volatile(
        "mma.sync.aligned.m16n8k16.row.col.f32.f16.f16.f32 "
        "{%0,%1,%2,%3}, {%4,%5,%6,%7}, {%8,%9}, {%0,%1,%2,%3};"
        : "+f"(c[0]), "+f"(c[1]), "+f"(c[2]), "+f"(c[3])
        : "r"(a[0]), "r"(a[1]), "r"(a[2]), "r"(a[3]), "r"(b0), "r"(b1));
}
__device__ __forceinline__ uint32_t pk2(__half lo, __half hi) {
    __half2 v(lo, hi);
    return *(uint32_t*)&v;
}

// ======================= fused conversion kernels =========================
// grid (8192, 3): y selects Q/K/V embedding -> g_x[y] (single fp16)
__global__ void conv_x_kernel(const float* __restrict__ q,
                              const float* __restrict__ k,
                              const float* __restrict__ v)
{
    const int z = blockIdx.y;
    const float* X = (z == 0) ? q : (z == 1) ? k : v;
    __half* dh = g_x[z];
    const size_t idx = (size_t)blockIdx.x * blockDim.x + threadIdx.x; // float4
    float4 vv = ((const float4*)X)[idx];
    ((__half2*)dh)[idx*2+0] = __half2(__float2half_rn(vv.x), __float2half_rn(vv.y));
    ((__half2*)dh)[idx*2+1] = __half2(__float2half_rn(vv.z), __float2half_rn(vv.w));
}

// grid (1024, 4): y selects WQ/WK/WV/WO; W f32 [K,N] -> W^T fp16 [N,K]
__global__ void conv_w_kernel(const float* __restrict__ wq,
                              const float* __restrict__ wk,
                              const float* __restrict__ wv,
                              const float* __restrict__ wo)
{
    const int z = blockIdx.y;
    const float* W = (z == 0) ? wq : (z == 1) ? wk : (z == 2) ? wv : wo;
    __half* dst = g_wt4[z];
    const int idx = blockIdx.x * blockDim.x + threadIdx.x;
    const int n  = idx >> 8;
    const int kq = (idx & 255) << 2;
    __half h[4];
    #pragma unroll
    for (int j = 0; j < 4; ++j)
        h[j] = __float2half_rn(W[(size_t)(kq + j) * DM + n]);
    const size_t o2 = ((size_t)n * DM + kq) >> 1;
    ((__half2*)dst)[o2+0] = __half2(h[0], h[1]);
    ((__half2*)dst)[o2+1] = __half2(h[2], h[3]);
}

// ============== HMMA GEMM: C[8192,1024] = X @ W (fp16 1-pass) =============
// 128x128 CTA tile, K-chunks of 32, cp.async double-buffered SMEM.
// 8 warps = 2(M) x 4(N); warp tile 64x32 = 4x4 m16n8k16 fragments.
// Buffers per stage: X, Wt (2 matrices) -> 2 CTAs/SM occupancy.
// blockIdx.z selects (X slot, W slot, dst) = (xsel+z, wsel+z, dsel+z).
#define MAT_BYTES (128*80)            // 10240 B
#define BUFB      (2*MAT_BYTES)       // X, Wt = 20480 B
#define GEMM_SMEM (2*BUFB)            // 40960 B

__global__ __launch_bounds__(256, 2)
void mma_gemm_kernel(float* __restrict__ Yplain, int xsel, int wsel, int dsel)
{
    extern __shared__ char smg[];
    const int tid  = threadIdx.x;
    const int lane = tid & 31;
    const int wid  = tid >> 5;
    const int wm   = wid >> 2;
    const int wn   = wid & 3;
    const int bm   = blockIdx.y * 128;
    const int bn   = blockIdx.x * 128;
    const uint32_t sbase = smem_u32(smg);

    const int z = blockIdx.z;
    const __half* Xh = g_x  [xsel + z];
    const __half* Wt = g_wt4[wsel + z];
    const int dst_sel = dsel + z;

    float acc[4][4][4];
    #pragma unroll
    for (int i = 0; i < 4; ++i)
        #pragma unroll
        for (int j = 0; j < 4; ++j)
            #pragma unroll
            for (int t = 0; t < 4; ++t) acc[i][j][t] = 0.f;

    auto load_chunk = [&](int kc, int b) {
        const uint32_t base = sbase + b*BUFB;
        #pragma unroll
        for (int t = 0; t < 2; ++t) {
            const int idx = tid + (t << 8);
            const int r = idx >> 2, c = idx & 3;
            const uint32_t so = (uint32_t)(r*80 + c*16);
            const size_t ea = (size_t)(bm + r)*DM + kc*32 + c*8;
            const size_t eb = (size_t)(bn + r)*DM + kc*32 + c*8;
            cp_async16(base +             so, Xh + ea);
            cp_async16(base + MAT_BYTES + so, Wt + eb);
        }
        CP_COMMIT();
    };

    load_chunk(0, 0);

    for (int kc = 0; kc < 32; ++kc) {
        const int b = kc & 1;
        if (kc < 31) { load_chunk(kc + 1, b ^ 1); CP_WAIT(1); }
        else         { CP_WAIT(0); }
        __syncthreads();

        const uint32_t abase = sbase + b*BUFB;
        const uint32_t bbase = abase + MAT_BYTES;

        #pragma unroll
        for (int ks = 0; ks < 2; ++ks) {
            const uint32_t colB = (uint32_t)(ks*32 + (lane >> 4)*16);

            uint32_t af[4][4];
            #pragma unroll
            for (int i = 0; i < 4; ++i) {
                const uint32_t ad = abase +
                    (uint32_t)((wm*64 + i*16 + (lane & 15))*80) + colB;
                ldsm_x4(af[i], ad);
            }
            uint32_t bq[4][2];
            #pragma unroll
            for (int jp = 0; jp < 2; ++jp) {
                uint32_t r4[4];
                const uint32_t bd = bbase +
                    (uint32_t)((wn*32 + jp*16 + (lane & 15))*80) + colB;
                ldsm_x4(r4, bd);
                bq[2*jp+0][0] = r4[0]; bq[2*jp+0][1] = r4[2];
                bq[2*jp+1][0] = r4[1]; bq[2*jp+1][1] = r4[3];
            }
            #pragma unroll
            for (int i = 0; i < 4; ++i)
                #pragma unroll
                for (int j = 0; j < 4; ++j)
                    mma16816(acc[i][j], af[i], bq[j][0], bq[j][1]);
        }
        __syncthreads();
    }

    // ---- epilogue: 0=Q fp16, 1=K fp16, 2=V fp32, 3=plain fp32
    const int tg = lane >> 2;
    const int t4 = lane & 3;
    #pragma unroll
    for (int i = 0; i < 4; ++i) {
        #pragma unroll
        for (int j = 0; j < 4; ++j) {
            const int m0 = bm + wm*64 + i*16 + tg;
            const int n0 = bn + wn*32 + j*8 + t4*2;
            #pragma unroll
            for (int half = 0; half < 2; ++half) {
                const int m = m0 + half*8;
                const float x = acc[i][j][half*2+0];
                const float y = acc[i][j][half*2+1];
                if (dst_sel <= 1) {
                    const int bb = m >> 11, s = m & (SS-1);
                    const int h  = n0 >> 6, d = n0 & (DH-1);
                    const size_t oi = ((size_t)((bb << 4) + h) * SS + s) * DH + d;
                    __half2 hv(__float2half_rn(x), __float2half_rn(y));
                    if (dst_sel == 0) *(__half2*)&g_qh[oi] = hv;
                    else              *(__half2*)&g_kh[oi] = hv;
                } else if (dst_sel == 2) {
                    const int bb = m >> 11, s = m & (SS-1);
                    const int h  = n0 >> 6, d = n0 & (DH-1);
                    *(float2*)&g_v[((size_t)((bb << 4) + h) * SS + s) * DH + d] =
                        make_float2(x, y);
                } else {
                    *(float2*)&Yplain[(size_t)m * DM + n0] = make_float2(x, y);
                }
            }
        }
    }
}

// =============== V^T transpose + fp16: g_v -> g_vth [bh][dh][s] ===========
__global__ void vt_split_kernel()
{
    __shared__ float t[64][65];
    const int bh = blockIdx.y;
    const int sb = blockIdx.x << 6;
    const int tid = threadIdx.x;
    #pragma unroll
    for (int i = 0; i < 4; ++i) {
        const int f = tid + (i << 8);
        const int s = f >> 4, d4 = (f & 15) << 2;
        float4 v = *(const float4*)&g_v[((size_t)bh*SS + sb + s)*DH + d4];
        t[s][d4+0] = v.x; t[s][d4+1] = v.y; t[s][d4+2] = v.z; t[s][d4+3] = v.w;
    }
    __syncthreads();
    const int d  = tid >> 2;
    const int s0 = (tid & 3) << 4;
    #pragma unroll
    for (int j = 0; j < 16; j += 2) {
        const size_t oi = ((size_t)bh*DH + d)*SS + sb + s0 + j;
        *(__half2*)&g_vth[oi] = __half2(__float2half_rn(t[s0+j][d]),
                                        __float2half_rn(t[s0+j+1][d]));
    }
}

// =================== vmean: mean over S of V per (bh, d) ==================
__global__ void vmean_kernel()
{
    __shared__ float red[512];
    const int bh = blockIdx.x;
    const int d  = threadIdx.x & 63;
    const int sc = threadIdx.x >> 6;
    float acc = 0.f;
    const int base = (bh << 11) + (sc << 8);
    #pragma unroll 8
    for (int s = 0; s < 256; ++s)
        acc += g_v[(size_t)(base + s) * DH + d];
    red[threadIdx.x] = acc;
    __syncthreads();
    if (sc == 0) {
        float t = 0.f;
        #pragma unroll
        for (int j = 0; j < 8; ++j) t += red[(j << 6) + d];
        g_vmean[(bh << 6) + d] = t * (1.0f/2048.0f);
    }
}

// =================== HMMA flash attention (fp16 1-pass) ===================
// CTA = (bh, q-tile of 128 rows), 256 threads = 8 warps; warp w owns rows
// w*16..w*16+15. Q fp16 resident; K/V fp16 single, 64-key tiles,
// double-buffered. 1/8 scale applied post-mma.
#define ATT_ROWB  144                 // smem row stride (128 B + 16 pad)
#define ATT_KMATB (64*ATT_ROWB)       // 9216  (K or V^T tile)
#define ATT_QMATB (128*ATT_ROWB)      // 18432 (Q tile)
#define ATT_KV(b) (ATT_QMATB + (b)*2*ATT_KMATB)
#define ATT_KINI  (ATT_QMATB + 4*ATT_KMATB)     // 55296
#define ATT_SMEM  (ATT_KINI + 512)              // 55808

__global__ __launch_bounds__(256, 1)
void attn_kernel(const int* __restrict__ K_ini)
{
    extern __shared__ char attsm[];
    const uint32_t sb = smem_u32(attsm);
    const int tid  = threadIdx.x;
    const int lane = tid & 31;
    const int w    = tid >> 5;                 // 0..7
    const int qt   = (SS/128 - 1) - blockIdx.x; // longest CTAs first
    const int bh   = blockIdx.y;
    const int b    = bh >> 4;
    const int h    = bh & 15;

    const size_t qkbase = (size_t)bh * SS * DH;   // [bh][s][dh]
    const size_t vtbase = (size_t)bh * DH * SS;   // [bh][dh][s]

    auto load_kv = [&](int kt, int bf) {
        const uint32_t kb = sb + ATT_KV(bf);
        #pragma unroll
        for (int i = 0; i < 2; ++i) {
            const int f = tid + (i << 8);
            const int r = f >> 3, c = f & 7;     // r 0..63
            const uint32_t so = (uint32_t)(r*ATT_ROWB + c*16);
            const size_t gk = qkbase + (size_t)(kt*64 + r)*DH + c*8;
            const size_t gv = vtbase + (size_t)r*SS + kt*64 + c*8;
            cp_async16(kb +             so, g_kh  + gk);
            cp_async16(kb + ATT_KMATB + so, g_vth + gv);
        }
        CP_COMMIT();
    };

    // ---- prologue: Q (128 rows) + K/V tile 0 + kini0
    #pragma unroll
    for (int i = 0; i < 4; ++i) {
        const int f = tid + (i << 8);
        const int r = f >> 3, c = f & 7;         // r 0..127
        const uint32_t so = (uint32_t)(r*ATT_ROWB + c*16);
        const size_t gq = qkbase + (size_t)(qt*128 + r)*DH + c*8;
        cp_async16(sb + so, g_qh + gq);
    }
    load_kv(0, 0);
    if (tid < 16)
        ((int4*)(attsm + ATT_KINI))[tid] = ((const int4*)(K_ini + b*SS))[tid];
    CP_WAIT(0);
    __syncthreads();

    // ---- Q A-fragments (resident)
    uint32_t qf[4][4];
    const uint32_t lrow16 = (uint32_t)((lane & 15) * ATT_ROWB);
    const uint32_t lcol   = (uint32_t)((lane >> 4) << 4);
    #pragma unroll
    for (int kd = 0; kd < 4; ++kd) {
        const uint32_t qa = sb + (uint32_t)(w*16*ATT_ROWB) + lrow16 + kd*32 + lcol;
        ldsm_x4(qf[kd], qa);
    }

    float o[8][4];
    #pragma unroll
    for (int jd = 0; jd < 8; ++jd)
        #pragma unroll
        for (int e = 0; e < 4; ++e) o[jd][e] = 0.f;
    float mrow[2] = {-3.0e38f, -3.0e38f};
    float lrow[2] = {0.f, 0.f};

    const int qr_loc = w*16 + (lane >> 2);     // tile-local row (half0), 0..127
    const int ktmax  = 2*qt + 1;

    for (int kt = 0; kt <= ktmax; ++kt) {
        const int buf = kt & 1;
        if (kt < ktmax) { load_kv(kt + 1, buf ^ 1); CP_WAIT(1); }
        else            { CP_WAIT(0); }
        __syncthreads();
        if (kt < ktmax && tid < 16)
            ((int4*)(attsm + ATT_KINI))[(buf ^ 1)*16 + tid] =
                ((const int4*)(K_ini + b*SS + (kt + 1)*64))[tid];

        // ---- scores S = Q.K^T (1-pass fp16)
        float s[8][4];
        #pragma unroll
        for (int jn = 0; jn < 8; ++jn)
            #pragma unroll
            for (int e = 0; e < 4; ++e) s[jn][e] = 0.f;

        const uint32_t kb = sb + ATT_KV(buf);
        #pragma unroll
        for (int nk = 0; nk < 4; ++nk) {
            #pragma unroll
            for (int kd = 0; kd < 4; ++kd) {
                uint32_t kf[4];
                const uint32_t ad = kb + (uint32_t)(nk*16*ATT_ROWB) + lrow16
                                  + kd*32 + lcol;
                ldsm_x4(kf, ad);
                mma16816(s[nk*2+0], qf[kd], kf[0], kf[2]);
                mma16816(s[nk*2+1], qf[kd], kf[1], kf[3]);
            }
        }

        // ---- scale 1/8, mask (pad + causal near diagonal), tile max
        const int* kini = (const int*)(attsm + ATT_KINI) + buf*64;
        const int needc = (kt >= 2*qt);
        float tmax[2] = {-3.0e38f, -3.0e38f};
        #pragma unroll
        for (int jn = 0; jn < 8; ++jn) {
            #pragma unroll
            for (int e = 0; e < 4; ++e) {
                const int col  = jn*8 + ((lane & 3) << 1) + (e & 1);
                const int half = e >> 1;
                bool masked = (kini[col] == 0);
                if (needc) masked = masked || (kt*64 + col > qt*128 + qr_loc + half*8);
                float sv = s[jn][e] * 0.125f;
                if (masked) sv -= NEG_BIG;       // exact -1e10 (fp32 absorb)
                s[jn][e] = sv;
                tmax[half] = fmaxf(tmax[half], sv);
            }
        }
        #pragma unroll
        for (int half = 0; half < 2; ++half) {
            tmax[half] = fmaxf(tmax[half], __shfl_xor_sync(0xffffffffu, tmax[half], 1));
            tmax[half] = fmaxf(tmax[half], __shfl_xor_sync(0xffffffffu, tmax[half], 2));
        }
        const float nm0 = fmaxf(mrow[0], tmax[0]);
        const float nm1 = fmaxf(mrow[1], tmax[1]);
        const float sc0 = __expf(mrow[0] - nm0);
        const float sc1 = __expf(mrow[1] - nm1);
        mrow[0] = nm0; mrow[1] = nm1;

        // ---- exp + P into A-frags (register-only, single fp16)
        uint32_t ap[4][4];
        float ls0 = 0.f, ls1 = 0.f;
        #pragma unroll
        for (int jn = 0; jn < 8; ++jn) {
            const float p0 = __expf(s[jn][0] - nm0);
            const float p1 = __expf(s[jn][1] - nm0);
            const float p2 = __expf(s[jn][2] - nm1);
            const float p3 = __expf(s[jn][3] - nm1);
            ls0 += p0 + p1; ls1 += p2 + p3;
            const int kp  = jn >> 1;
            const int sub = (jn & 1) << 1;
            ap[kp][sub+0] = pk2(__float2half_rn(p0), __float2half_rn(p1));
            ap[kp][sub+1] = pk2(__float2half_rn(p2), __float2half_rn(p3));
        }
        ls0 += __shfl_xor_sync(0xffffffffu, ls0, 1);
        ls0 += __shfl_xor_sync(0xffffffffu, ls0, 2);
        ls1 += __shfl_xor_sync(0xffffffffu, ls1, 1);
        ls1 += __shfl_xor_sync(0xffffffffu, ls1, 2);
        lrow[0] = lrow[0]*sc0 + ls0;
        lrow[1] = lrow[1]*sc1 + ls1;
        #pragma unroll
        for (int jd = 0; jd < 8; ++jd) {
            o[jd][0] *= sc0; o[jd][1] *= sc0;
            o[jd][2] *= sc1; o[jd][3] *= sc1;
        }

        // ---- O += P.V (1-pass fp16)
        const uint32_t vb = kb + ATT_KMATB;
        #pragma unroll
        for (int nd = 0; nd < 4; ++nd) {
            #pragma unroll
            for (int kp = 0; kp < 4; ++kp) {
                uint32_t vf[4];
                const uint32_t ad = vb + (uint32_t)(nd*16*ATT_ROWB) + lrow16
                                  + kp*32 + lcol;
                ldsm_x4(vf, ad);
                mma16816(o[nd*2+0], ap[kp], vf[0], vf[2]);
                mma16816(o[nd*2+1], ap[kp], vf[1], vf[3]);
            }
        }
        __syncthreads();   // protect buf reuse by next iteration's prefetch
    }

    // ---- epilogue: ctx fp16 into the WO-GEMM input (slot 0)
    #pragma unroll
    for (int half = 0; half < 2; ++half) {
        const int row = qr_loc + half*8;
        const size_t mg = (size_t)(b*SS + qt*128 + row);
        const float inv = 1.0f / lrow[half];
        const bool fullmask = (mrow[half] < -1e9f);
        #pragma unroll
        for (int jd = 0; jd < 8; ++jd) {
            const int d = jd*8 + ((lane & 3) << 1);
            float v0, v1;
            if (fullmask) {
                // reference: all scores exactly -1e10 -> uniform softmax over
                // ALL 2048 keys -> mean of V
                v0 = g_vmean[bh*64 + d];
                v1 = g_vmean[bh*64 + d + 1];
            } else {
                v0 = o[jd][half*2+0] * inv;
                v1 = o[jd][half*2+1] * inv;
            }
            const size_t oi = mg*DM + h*64 + d;
            *(__half2*)&g_x[0][oi] =
                __half2(__float2half_rn(v0), __float2half_rn(v1));
        }
    }
}

// ============================ launch ======================================
extern "C" void kernel_launch(void* const* d_in, const int* in_sizes, int n_in,
                              void* d_out, int out_size)
{
    const float* Q_emb = (const float*)d_in[0];
    const float* K_emb = (const float*)d_in[1];
    const float* V_emb = (const float*)d_in[2];
    const int*   K_ini = (const int*)  d_in[4];
    const float* WQ    = (const float*)d_in[5];
    const float* WK    = (const float*)d_in[6];
    const float* WV    = (const float*)d_in[7];
    const float* WO    = (const float*)d_in[8];
    float* out = (float*)d_out;
    (void)in_sizes; (void)n_in; (void)out_size;

    cudaFuncSetAttribute(mma_gemm_kernel,
                         cudaFuncAttributeMaxDynamicSharedMemorySize, GEMM_SMEM);
    cudaFuncSetAttribute(attn_kernel,
                         cudaFuncAttributeMaxDynamicSharedMemorySize, ATT_SMEM);

    // fused conversions (one launch each)
    conv_w_kernel<<<dim3((DM*256)/256, 4), 256>>>(WQ, WK, WV, WO);
    conv_x_kernel<<<dim3((MM*DM/4)/256, 3), 256>>>(Q_emb, K_emb, V_emb);

    // fused QKV projections: grid.z = 3 -> (X_z, W_z, dst_z)
    mma_gemm_kernel<<<dim3(DM/128, MM/128, 3), 256, GEMM_SMEM>>>(nullptr, 0, 0, 0);

    vt_split_kernel<<<dim3(SS/64, BB*HH), 256>>>();   // -> V^T fp16
    vmean_kernel<<<BB*HH, 512>>>();

    attn_kernel<<<dim3(SS/128, BB*HH), 256, ATT_SMEM>>>(K_ini); // -> ctx fp16

    // output projection: ctx (slot 0) @ WO -> out
    mma_gemm_kernel<<<dim3(DM/128, MM/128, 1), 256, GEMM_SMEM>>>(out, 0, 3, 3);
}